// round 12
// baseline (speedup 1.0000x reference)
#include <cuda_runtime.h>
#include <cstdint>
#include <cstddef>

// Problem constants
#define BB 4
#define LL 1024
#define DD 1024
#define HH 16
#define INNER 1024          // H*HD
#define M1 4096             // B*L
#define QKV_N 3072          // 3*INNER

// Scratch (static device allocations — allowed)
__device__ uint16_t g_xh[(size_t)M1 * DD];      // x split (fp16 hi)
__device__ uint16_t g_xl[(size_t)M1 * DD];      // x split (fp16 lo)
__device__ uint16_t g_wqh[(size_t)QKV_N * DD];  // w_qkv fp16 (1-term)
__device__ uint16_t g_woh[(size_t)DD * INNER];  // w_out fp16 (1-term)
__device__ uint16_t g_qh[(size_t)M1 * QKV_N];   // qkv split bf16 hi (Q,K used)
__device__ uint16_t g_ql[(size_t)M1 * QKV_N];   // qkv split bf16 lo
__device__ uint16_t g_vth[(size_t)HH * 64 * BB * LL];  // V^T bf16 hi [e][b][l]
__device__ uint16_t g_vtl[(size_t)HH * 64 * BB * LL];  // V^T bf16 lo
__device__ uint16_t g_ah[(size_t)M1 * INNER];   // attention out (fp16 hi)
__device__ uint16_t g_al[(size_t)M1 * INNER];   // attention out (fp16 lo)

// ===========================================================================
// Portable PTX helpers
// ===========================================================================
__device__ __forceinline__ uint32_t smem_u32(const void* p) {
    uint32_t a;
    asm("{ .reg .u64 t; cvta.to.shared.u64 t, %1; cvt.u32.u64 %0, t; }"
        : "=r"(a) : "l"(p));
    return a;
}
__device__ __forceinline__ void cp_async16(uint32_t dst, const void* src) {
    asm volatile("cp.async.cg.shared.global [%0], [%1], 16;"
                 :: "r"(dst), "l"(src) : "memory");
}
#define CP_COMMIT() asm volatile("cp.async.commit_group;" ::: "memory")
#define CP_WAIT(n)  asm volatile("cp.async.wait_group %0;" :: "n"(n) : "memory")

__device__ __forceinline__ void ldsm_x4(uint32_t* r, uint32_t addr) {
    asm volatile("ldmatrix.sync.aligned.m8n8.x4.shared.b16 {%0,%1,%2,%3}, [%4];"
                 : "=r"(r[0]), "=r"(r[1]), "=r"(r[2]), "=r"(r[3]) : "r"(addr));
}
__device__ __forceinline__ void mma_bf16(float* d, const uint32_t* a,
                                         const uint32_t* b) {
    asm volatile(
        "mma.sync.aligned.m16n8k16.row.col.f32.bf16.bf16.f32 "
        "{%0,%1,%2,%3}, {%4,%5,%6,%7}, {%8,%9}, {%0,%1,%2,%3};"
        : "+f"(d[0]), "+f"(d[1]), "+f"(d[2]), "+f"(d[3])
        : "r"(a[0]), "r"(a[1]), "r"(a[2]), "r"(a[3]), "r"(b[0]), "r"(b[1]));
}
__device__ __forceinline__ void mma_f16(float* d, const uint32_t* a,
                                        const uint32_t* b) {
    asm volatile(
        "mma.sync.aligned.m16n8k16.row.col.f32.f16.f16.f32 "
        "{%0,%1,%2,%3}, {%4,%5,%6,%7}, {%8,%9}, {%0,%1,%2,%3};"
        : "+f"(d[0]), "+f"(d[1]), "+f"(d[2]), "+f"(d[3])
        : "r"(a[0]), "r"(a[1]), "r"(a[2]), "r"(a[3]), "r"(b[0]), "r"(b[1]));
}
// ---- bf16 pack ----
__device__ __forceinline__ uint32_t cvt2bf16(float e, float o) {
    uint32_t r;
    asm("cvt.rn.bf16x2.f32 %0, %1, %2;" : "=r"(r) : "f"(o), "f"(e));
    return r;
}
__device__ __forceinline__ void pack_pair(float e, float o,
                                          uint32_t& hi, uint32_t& lo) {
    uint32_t h = cvt2bf16(e, o);
    float re = e - __uint_as_float(h << 16);
    float ro = o - __uint_as_float(h & 0xffff0000u);
    hi = h;
    lo = cvt2bf16(re, ro);
}
// ---- fp16 pack ----
__device__ __forceinline__ uint32_t cvt2f16(float e, float o) {
    uint32_t r;
    asm("cvt.rn.f16x2.f32 %0, %1, %2;" : "=r"(r) : "f"(o), "f"(e));
    return r;
}
__device__ __forceinline__ float f16lo2f(uint32_t h) {
    float f;
    asm("{ .reg .f16 a, b; mov.b32 {a, b}, %1; cvt.f32.f16 %0, a; }"
        : "=f"(f) : "r"(h));
    return f;
}
__device__ __forceinline__ float f16hi2f(uint32_t h) {
    float f;
    asm("{ .reg .f16 a, b; mov.b32 {a, b}, %1; cvt.f32.f16 %0, b; }"
        : "=f"(f) : "r"(h));
    return f;
}
__device__ __forceinline__ void pack_pair_f16(float e, float o,
                                              uint32_t& hi, uint32_t& lo) {
    uint32_t h = cvt2f16(e, o);
    float re = e - f16lo2f(h);
    float ro = o - f16hi2f(h);
    hi = h;
    lo = cvt2f16(re, ro);
}
__device__ __forceinline__ float fast_ex2(float x) {
    float r;
    asm("ex2.approx.ftz.f32 %0, %1;" : "=f"(r) : "f"(x));
    return r;
}

// ===========================================================================
// Split / round kernels (memory-bound)
// ===========================================================================
__global__ __launch_bounds__(256) void split_f16_kernel(
    const float* __restrict__ src, uint16_t* __restrict__ hi,
    uint16_t* __restrict__ lo, int n4)
{
    int idx = blockIdx.x * blockDim.x + threadIdx.x;
    if (idx >= n4) return;
    float4 v = ((const float4*)src)[idx];
    uint32_t h0, l0, h1, l1;
    pack_pair_f16(v.x, v.y, h0, l0);
    pack_pair_f16(v.z, v.w, h1, l1);
    ((uint2*)hi)[idx] = make_uint2(h0, h1);
    ((uint2*)lo)[idx] = make_uint2(l0, l1);
}
__global__ __launch_bounds__(256) void round_f16_kernel(
    const float* __restrict__ src, uint16_t* __restrict__ dst, int n4)
{
    int idx = blockIdx.x * blockDim.x + threadIdx.x;
    if (idx >= n4) return;
    float4 v = ((const float4*)src)[idx];
    ((uint2*)dst)[idx] = make_uint2(cvt2f16(v.x, v.y), cvt2f16(v.z, v.w));
}

// ===========================================================================
// FP16 2-term GEMM (NT): C = (Ah+Al) Bh^T. 128x128x32, 8 warps 2Mx4N.
// THREE-stage cp.async pipeline: loads get 2 chunk-times to retire.
// SPLIT_OUT: Q,K cols -> bf16 hi/lo; V cols (n0>=2048) -> transposed VT.
// ===========================================================================
#define BSTR 40
#define BTILE_B (128 * BSTR * 2)       // 10240 bytes
#define BGEMM_SMEM (9 * BTILE_B)       // 3 stages x (Ah,Al,Bh) = 92160
#define TSTR 136                        // transpose tile stride (elems)

template <bool SPLIT_OUT>
__global__ __launch_bounds__(256) void f16_gemm(
    const uint16_t* __restrict__ Ah, const uint16_t* __restrict__ Al,
    const uint16_t* __restrict__ Bh,
    const float* __restrict__ bias, float* __restrict__ C,
    uint16_t* __restrict__ outH, uint16_t* __restrict__ outL,
    uint16_t* __restrict__ vtH, uint16_t* __restrict__ vtL,
    int M, int N, int K)
{
    extern __shared__ char smraw[];
    const uint32_t sb = smem_u32(smraw);
    const int tid  = threadIdx.x;
    const int wid  = tid >> 5, lane = tid & 31;
    const int m0   = blockIdx.y << 7, n0 = blockIdx.x << 7;
    const int wm   = (wid & 1) << 6;
    const int wn   = (wid >> 1) << 5;

    uint32_t stg[3] = { sb, sb + 3 * BTILE_B, sb + 6 * BTILE_B };

    const int lrow = tid >> 2;
    const int lc   = tid & 3;
    const uint32_t so0 = (uint32_t)(lrow * BSTR * 2 + lc * 16);
    const uint32_t so1 = (uint32_t)((lrow + 64) * BSTR * 2 + lc * 16);
    const uint16_t* gAh = Ah + (size_t)(m0 + lrow) * K + lc * 8;
    const uint16_t* gAl = Al + (size_t)(m0 + lrow) * K + lc * 8;
    const uint16_t* gBh = Bh + (size_t)(n0 + lrow) * K + lc * 8;
    const size_t r64 = (size_t)64 * K;

    float acc[4][4][4];
#pragma unroll
    for (int i = 0; i < 4; i++)
#pragma unroll
        for (int j = 0; j < 4; j++)
#pragma unroll
            for (int k = 0; k < 4; k++) acc[i][j][k] = 0.f;

    const uint32_t arow = (uint32_t)(wm + (lane & 15));
    const uint32_t acol = (uint32_t)((lane >> 4) << 3);
    const uint32_t brow = (uint32_t)(wn + (lane & 7) + ((lane >> 4) & 1) * 8);
    const uint32_t bcol = (uint32_t)(((lane >> 3) & 1) << 3);

    const int NCH = K >> 5;

    // prologue: chunks 0 and 1 into stages 0,1 (separate commit groups)
#pragma unroll
    for (int pc = 0; pc < 2; pc++) {
        const int k0 = pc << 5;
        uint32_t d = stg[pc];
        cp_async16(d + 0 * BTILE_B + so0, gAh + k0);
        cp_async16(d + 0 * BTILE_B + so1, gAh + r64 + k0);
        cp_async16(d + 1 * BTILE_B + so0, gAl + k0);
        cp_async16(d + 1 * BTILE_B + so1, gAl + r64 + k0);
        cp_async16(d + 2 * BTILE_B + so0, gBh + k0);
        cp_async16(d + 2 * BTILE_B + so1, gBh + r64 + k0);
        CP_COMMIT();
    }

    int s = 0;
    for (int ch = 0; ch < NCH; ch++) {
        if (ch + 1 < NCH) { CP_WAIT(1); } else { CP_WAIT(0); }
        __syncthreads();   // chunk ch visible; reads of stage s2 (ch-1) done
        if (ch + 2 < NCH) {
            const int k0 = (ch + 2) << 5;
            int s2 = s + 2; if (s2 >= 3) s2 -= 3;
            uint32_t d = stg[s2];
            cp_async16(d + 0 * BTILE_B + so0, gAh + k0);
            cp_async16(d + 0 * BTILE_B + so1, gAh + r64 + k0);
            cp_async16(d + 1 * BTILE_B + so0, gAl + k0);
            cp_async16(d + 1 * BTILE_B + so1, gAl + r64 + k0);
            cp_async16(d + 2 * BTILE_B + so0, gBh + k0);
            cp_async16(d + 2 * BTILE_B + so1, gBh + r64 + k0);
            CP_COMMIT();
        }

        const uint32_t AHB = stg[s], ALB = stg[s] + BTILE_B;
        const uint32_t BHB = stg[s] + 2 * BTILE_B;

#pragma unroll
        for (int ks = 0; ks < 2; ks++) {
            const uint32_t kadd = (uint32_t)(ks * 32);   // bytes
            uint32_t bh_[2][4];
#pragma unroll
            for (int j = 0; j < 2; j++)
                ldsm_x4(bh_[j], BHB + ((brow + j * 16) * BSTR + bcol) * 2 + kadd);
#pragma unroll
            for (int mip = 0; mip < 2; mip++) {
                const uint32_t off0 = ((arow + (2 * mip) * 16) * BSTR + acol) * 2 + kadd;
                const uint32_t off1 = ((arow + (2 * mip + 1) * 16) * BSTR + acol) * 2 + kadd;
                uint32_t ah0[4], ah1[4], al0[4], al1[4];
                ldsm_x4(ah0, AHB + off0);
                ldsm_x4(ah1, AHB + off1);
                ldsm_x4(al0, ALB + off0);
                ldsm_x4(al1, ALB + off1);
#pragma unroll
                for (int nj = 0; nj < 4; nj++)
                    mma_f16(acc[2 * mip][nj],     ah0, bh_[nj >> 1] + (nj & 1) * 2);
#pragma unroll
                for (int nj = 0; nj < 4; nj++)
                    mma_f16(acc[2 * mip + 1][nj], ah1, bh_[nj >> 1] + (nj & 1) * 2);
#pragma unroll
                for (int nj = 0; nj < 4; nj++)
                    mma_f16(acc[2 * mip][nj],     al0, bh_[nj >> 1] + (nj & 1) * 2);
#pragma unroll
                for (int nj = 0; nj < 4; nj++)
                    mma_f16(acc[2 * mip + 1][nj], al1, bh_[nj >> 1] + (nj & 1) * 2);
            }
        }
        s = (s + 1 == 3) ? 0 : s + 1;
    }

    const int rbase = m0 + wm + (lane >> 2);
    const int cbase = n0 + wn + ((lane & 3) << 1);

    if (SPLIT_OUT && n0 >= 2 * INNER) {
        // ---- V columns: transpose via smem, store to VT global layout ----
        uint16_t* T = (uint16_t*)smraw;
        const int b  = m0 >> 10;
        const int l0 = m0 & 1023;
#pragma unroll
        for (int pass = 0; pass < 2; pass++) {
            __syncthreads();
            const int rloc = wm + (lane >> 2);
            const int cloc = wn + ((lane & 3) << 1);
#pragma unroll
            for (int nj = 0; nj < 4; nj++) {
#pragma unroll
                for (int mi = 0; mi < 4; mi++) {
                    uint32_t h0, l0_, h1, l1_;
                    pack_pair(acc[mi][nj][0], acc[mi][nj][1], h0, l0_);
                    pack_pair(acc[mi][nj][2], acc[mi][nj][3], h1, l1_);
                    uint32_t w0 = pass ? l0_ : h0;
                    uint32_t w1 = pass ? l1_ : h1;
                    int c = cloc + nj * 8;
                    int r = rloc + mi * 16;
                    T[c * TSTR + r]           = (uint16_t)(w0 & 0xffffu);
                    T[(c + 1) * TSTR + r]     = (uint16_t)(w0 >> 16);
                    T[c * TSTR + r + 8]       = (uint16_t)(w1 & 0xffffu);
                    T[(c + 1) * TSTR + r + 8] = (uint16_t)(w1 >> 16);
                }
            }
            __syncthreads();
            uint16_t* dstbuf = pass ? vtL : vtH;
            // Drain FULL tile: 128 cols x 16 8-row units.
#pragma unroll
            for (int i = 0; i < 8; i++) {
                int idx = tid + (i << 8);
                int c = idx >> 4, u = idx & 15;
                int e = n0 - 2 * INNER + c;
                size_t dst = ((size_t)e * BB + b) * LL + l0 + u * 8;
                *(uint4*)(dstbuf + dst) = *(const uint4*)(T + c * TSTR + u * 8);
            }
        }
    } else {
#pragma unroll
        for (int nj = 0; nj < 4; nj++) {
            const int col = cbase + nj * 8;
            if (SPLIT_OUT) {
#pragma unroll
                for (int mi = 0; mi < 4; mi++) {
                    const int r0 = rbase + mi * 16;
                    uint32_t h0, l0, h1, l1;
                    pack_pair(acc[mi][nj][0], acc[mi][nj][1], h0, l0);
                    pack_pair(acc[mi][nj][2], acc[mi][nj][3], h1, l1);
                    *(uint32_t*)(outH + (size_t)r0 * N + col) = h0;
                    *(uint32_t*)(outL + (size_t)r0 * N + col) = l0;
                    *(uint32_t*)(outH + (size_t)(r0 + 8) * N + col) = h1;
                    *(uint32_t*)(outL + (size_t)(r0 + 8) * N + col) = l1;
                }
            } else {
                float b0 = bias[col], b1 = bias[col + 1];
#pragma unroll
                for (int mi = 0; mi < 4; mi++) {
                    const int r0 = rbase + mi * 16;
                    float2 v0 = { acc[mi][nj][0] + b0, acc[mi][nj][1] + b1 };
                    float2 v1 = { acc[mi][nj][2] + b0, acc[mi][nj][3] + b1 };
                    *(float2*)(C + (size_t)r0 * N + col) = v0;
                    *(float2*)(C + (size_t)(r0 + 8) * N + col) = v1;
                }
            }
        }
    }
}

// ===========================================================================
// Tensor-core attention, bf16 hi/lo split. V pre-transposed (VT layout).
// KV tiles now double-buffered via cp.async (wait->sync->prefetch->compute,
// the exact skeleton validated in the GEMM mainloop).
// ===========================================================================
#define AT_STR 72
#define AQH 0
#define AQL (128 * AT_STR)
#define AKV0 (2 * 128 * AT_STR)            // elems
#define AMAT (64 * AT_STR)                  // one 64x64 matrix (elems)
#define ASTG (4 * AMAT)                     // stage stride (elems)
#define AT_ELEMS (AKV0 + 2 * ASTG)
#define AT_SMEM_BYTES (AT_ELEMS * 2)        // 110592 bytes

__global__ __launch_bounds__(256) void attn_kernel(
    const uint16_t* __restrict__ qh, const uint16_t* __restrict__ ql,
    const uint16_t* __restrict__ vth, const uint16_t* __restrict__ vtl,
    uint16_t* __restrict__ oh, uint16_t* __restrict__ ol)
{
    extern __shared__ uint16_t sm16[];
    const uint32_t sb = smem_u32(sm16);
    const int tid = threadIdx.x, wid = tid >> 5, lane = tid & 31;
    const int bh = blockIdx.x, b = bh >> 4, h = bh & 15;
    const int q0 = blockIdx.y << 7;
    const size_t rowbase = (size_t)b * LL;

    // ---- Q tile (plain loads, once) ----
#pragma unroll
    for (int i = 0; i < 4; i++) {
        int idx = tid + (i << 8);
        int r = idx >> 3, c8 = idx & 7;
        size_t g = (rowbase + q0 + r) * QKV_N + h * 64 + c8 * 8;
        *(uint4*)(sm16 + AQH + r * AT_STR + c8 * 8) = *(const uint4*)(qh + g);
        *(uint4*)(sm16 + AQL + r * AT_STR + c8 * 8) = *(const uint4*)(ql + g);
    }

    // ---- per-thread KV load slots ----
    const int lr = tid >> 3, lc8 = tid & 7;    // lr 0..31 (+32), lc8 0..7
    const uint32_t dloc0 = (uint32_t)(lr * AT_STR + lc8 * 8) * 2;
    const uint32_t dloc1 = (uint32_t)((lr + 32) * AT_STR + lc8 * 8) * 2;
    const uint32_t KV0 = sb + (uint32_t)AKV0 * 2;
    const uint32_t STGB = (uint32_t)ASTG * 2;
    const uint32_t MATB = (uint32_t)AMAT * 2;

    // prologue: KV tile 0 into stage 0
    {
        uint32_t d = KV0;
#pragma unroll
        for (int i = 0; i < 2; i++) {
            int r = lr + i * 32;
            uint32_t dl = i ? dloc1 : dloc0;
            size_t gk = (rowbase + r) * QKV_N + INNER + h * 64 + lc8 * 8;
            size_t gv = ((size_t)(h * 64 + r) * BB + b) * LL + lc8 * 8;
            cp_async16(d + 0 * MATB + dl, qh + gk);
            cp_async16(d + 1 * MATB + dl, ql + gk);
            cp_async16(d + 2 * MATB + dl, vth + gv);
            cp_async16(d + 3 * MATB + dl, vtl + gv);
        }
    }
    CP_COMMIT();
    __syncthreads();   // Q tile visible for ldsm

    uint32_t qfh[4][4], qfl[4][4];
    {
        const uint32_t qrow = (uint32_t)((wid << 4) + (lane & 15));
        const uint32_t cc = (uint32_t)((lane >> 4) << 3);
#pragma unroll
        for (int ks = 0; ks < 4; ks++) {
            uint32_t off = (uint32_t)(qrow * AT_STR + ks * 16 + cc) * 2;
            ldsm_x4(qfh[ks], sb + AQH * 2 + off);
            ldsm_x4(qfl[ks], sb + AQL * 2 + off);
        }
    }

    float oacc[8][4];
#pragma unroll
    for (int i = 0; i < 8; i++)
#pragma unroll
        for (int j = 0; j < 4; j++) oacc[i][j] = 0.f;
    float ls0 = 0.f, ls1 = 0.f;

    const float CE = 0.125f * 1.4426950408889634f;

    for (int kt = 0; kt < 16; kt++) {
        CP_WAIT(0);
        __syncthreads();   // KV(kt) visible; reads of other stage done

        if (kt + 1 < 16) {
            uint32_t d = KV0 + ((kt + 1) & 1) * STGB;
#pragma unroll
            for (int i = 0; i < 2; i++) {
                int r = lr + i * 32;
                uint32_t dl = i ? dloc1 : dloc0;
                size_t gk = (rowbase + (kt + 1) * 64 + r) * QKV_N + INNER
                            + h * 64 + lc8 * 8;
                size_t gv = ((size_t)(h * 64 + r) * BB + b) * LL
                            + (kt + 1) * 64 + lc8 * 8;
                cp_async16(d + 0 * MATB + dl, qh + gk);
                cp_async16(d + 1 * MATB + dl, ql + gk);
                cp_async16(d + 2 * MATB + dl, vth + gv);
                cp_async16(d + 3 * MATB + dl, vtl + gv);
            }
            CP_COMMIT();
        }

        const uint32_t base = KV0 + (kt & 1) * STGB;
        const uint32_t KHB = base,            KLB = base + MATB;
        const uint32_t VHB = base + 2 * MATB, VLB = base + 3 * MATB;

        // ---- S = Q K^T (3-term split) ----
        float p[8][4];
#pragma unroll
        for (int i = 0; i < 8; i++)
#pragma unroll
            for (int j = 0; j < 4; j++) p[i][j] = 0.f;

#pragma unroll
        for (int ks = 0; ks < 4; ks++) {
#pragma unroll
            for (int njp = 0; njp < 4; njp++) {
                uint32_t kh[4], kl[4];
                uint32_t roff = (uint32_t)(njp * 16 + (lane & 7)
                                           + ((lane >> 4) & 1) * 8);
                uint32_t coff = (uint32_t)(ks * 16 + ((lane >> 3) & 1) * 8);
                uint32_t off = (roff * AT_STR + coff) * 2;
                ldsm_x4(kh, KHB + off);
                ldsm_x4(kl, KLB + off);
                mma_bf16(p[2 * njp],     qfh[ks], kh);
                mma_bf16(p[2 * njp + 1], qfh[ks], kh + 2);
                mma_bf16(p[2 * njp],     qfh[ks], kl);
                mma_bf16(p[2 * njp + 1], qfh[ks], kl + 2);
                mma_bf16(p[2 * njp],     qfl[ks], kh);
                mma_bf16(p[2 * njp + 1], qfl[ks], kh + 2);
            }
        }

        // ---- exp (clamped) + row-sum ----
#pragma unroll
        for (int nt = 0; nt < 8; nt++) {
#pragma unroll
            for (int q = 0; q < 4; q++) {
                float a_ = fminf(p[nt][q] * CE, 80.f);
                p[nt][q] = fast_ex2(a_);
            }
            ls0 += p[nt][0] + p[nt][1];
            ls1 += p[nt][2] + p[nt][3];
        }

        // ---- repack P -> A-frags hi/lo (bf16) ----
        uint32_t pah[4][4], pal[4][4];
#pragma unroll
        for (int ks = 0; ks < 4; ks++) {
            pack_pair(p[2 * ks][0],     p[2 * ks][1],     pah[ks][0], pal[ks][0]);
            pack_pair(p[2 * ks][2],     p[2 * ks][3],     pah[ks][1], pal[ks][1]);
            pack_pair(p[2 * ks + 1][0], p[2 * ks + 1][1], pah[ks][2], pal[ks][2]);
            pack_pair(p[2 * ks + 1][2], p[2 * ks + 1][3], pah[ks][3], pal[ks][3]);
        }

        // ---- O += P V ----
#pragma unroll
        for (int ks = 0; ks < 4; ks++) {
#pragma unroll
            for (int dtp = 0; dtp < 4; dtp++) {
                uint32_t vh[4], vl[4];
                uint32_t roff = (uint32_t)(dtp * 16 + (lane & 7)
                                           + ((lane >> 4) & 1) * 8);
                uint32_t coff = (uint32_t)(ks * 16 + ((lane >> 3) & 1) * 8);
                uint32_t off = (roff * AT_STR + coff) * 2;
                ldsm_x4(vh, VHB + off);
                ldsm_x4(vl, VLB + off);
                mma_bf16(oacc[2 * dtp],     pah[ks], vh);
                mma_bf16(oacc[2 * dtp + 1], pah[ks], vh + 2);
                mma_bf16(oacc[2 * dtp],     pal[ks], vh);
                mma_bf16(oacc[2 * dtp + 1], pal[ks], vh + 2);
                mma_bf16(oacc[2 * dtp],     pah[ks], vl);
                mma_bf16(oacc[2 * dtp + 1], pah[ks], vl + 2);
            }
        }
    }

    // ---- epilogue: normalize + fp16 split-store ----
    ls0 += __shfl_xor_sync(0xffffffffu, ls0, 1);
    ls0 += __shfl_xor_sync(0xffffffffu, ls0, 2);
    ls1 += __shfl_xor_sync(0xffffffffu, ls1, 1);
    ls1 += __shfl_xor_sync(0xffffffffu, ls1, 2);
    const float i0 = 1.f / fmaxf(ls0, 1e-30f);
    const float i1 = 1.f / fmaxf(ls1, 1e-30f);

    const int r0 = q0 + (wid << 4) + (lane >> 2);
    const int col = h * 64 + ((lane & 3) << 1);
#pragma unroll
    for (int dt = 0; dt < 8; dt++) {
        uint32_t h0, l0, h1, l1;
        pack_pair_f16(oacc[dt][0] * i0, oacc[dt][1] * i0, h0, l0);
        pack_pair_f16(oacc[dt][2] * i1, oacc[dt][3] * i1, h1, l1);
        size_t g0 = (rowbase + r0) * INNER + col + dt * 8;
        size_t g1 = (rowbase + r0 + 8) * INNER + col + dt * 8;
        *(uint32_t*)(oh + g0) = h0;
        *(uint32_t*)(ol + g0) = l0;
        *(uint32_t*)(oh + g1) = h1;
        *(uint32_t*)(ol + g1) = l1;
    }
}

// ---------------------------------------------------------------------------
// In-place LayerNorm (biased variance), one 256-thread block per row.
// ---------------------------------------------------------------------------
__global__ __launch_bounds__(256) void ln_kernel(
    float* __restrict__ Y, const float* __restrict__ gamma,
    const float* __restrict__ beta)
{
    const int row = blockIdx.x;
    float* y = Y + (size_t)row * DD;
    const int tid = threadIdx.x;

    float v[4];
    float s = 0.f, ss = 0.f;
#pragma unroll
    for (int i = 0; i < 4; i++) {
        v[i] = y[tid + (i << 8)];
        s += v[i];
        ss += v[i] * v[i];
    }
#pragma unroll
    for (int o = 16; o; o >>= 1) {
        s  += __shfl_xor_sync(0xffffffffu, s, o);
        ss += __shfl_xor_sync(0xffffffffu, ss, o);
    }
    __shared__ float rs[8], rss[8], mv[2];
    int w = tid >> 5, lane = tid & 31;
    if (!lane) { rs[w] = s; rss[w] = ss; }
    __syncthreads();
    if (tid == 0) {
        float S = 0.f, SS = 0.f;
#pragma unroll
        for (int i = 0; i < 8; i++) { S += rs[i]; SS += rss[i]; }
        float mean = S * (1.f / 1024.f);
        float var  = SS * (1.f / 1024.f) - mean * mean;
        mv[0] = mean;
        mv[1] = rsqrtf(var + 1e-5f);
    }
    __syncthreads();
    float mean = mv[0], rstd = mv[1];
#pragma unroll
    for (int i = 0; i < 4; i++) {
        int d = tid + (i << 8);
        y[d] = (v[i] - mean) * rstd * gamma[d] + beta[d];
    }
}

// ---------------------------------------------------------------------------
// Launch
// ---------------------------------------------------------------------------
extern "C" void kernel_launch(void* const* d_in, const int* in_sizes, int n_in,
                              void* d_out, int out_size)
{
    const float* x     = (const float*)d_in[0];
    const float* w_qkv = (const float*)d_in[2];
    const float* w_out = (const float*)d_in[3];
    const float* b_out = (const float*)d_in[4];
    const float* gamma = (const float*)d_in[5];
    const float* beta  = (const float*)d_in[6];
    float* out = (float*)d_out;

    uint16_t *xh, *xl, *wqh, *woh, *qh, *ql, *vth, *vtl, *ah, *al;
    cudaGetSymbolAddress((void**)&xh,  g_xh);
    cudaGetSymbolAddress((void**)&xl,  g_xl);
    cudaGetSymbolAddress((void**)&wqh, g_wqh);
    cudaGetSymbolAddress((void**)&woh, g_woh);
    cudaGetSymbolAddress((void**)&qh,  g_qh);
    cudaGetSymbolAddress((void**)&ql,  g_ql);
    cudaGetSymbolAddress((void**)&vth, g_vth);
    cudaGetSymbolAddress((void**)&vtl, g_vtl);
    cudaGetSymbolAddress((void**)&ah,  g_ah);
    cudaGetSymbolAddress((void**)&al,  g_al);

    cudaFuncSetAttribute(f16_gemm<true>,
                         cudaFuncAttributeMaxDynamicSharedMemorySize,
                         BGEMM_SMEM);
    cudaFuncSetAttribute(f16_gemm<false>,
                         cudaFuncAttributeMaxDynamicSharedMemorySize,
                         BGEMM_SMEM);
    cudaFuncSetAttribute(attn_kernel,
                         cudaFuncAttributeMaxDynamicSharedMemorySize,
                         AT_SMEM_BYTES);

    // 0) Split x (fp16 2-term); round weights (fp16 1-term)
    split_f16_kernel<<<(M1 * DD / 4 + 255) / 256, 256>>>(x, xh, xl, M1 * DD / 4);
    round_f16_kernel<<<(QKV_N * DD / 4 + 255) / 256, 256>>>(w_qkv, wqh,
                                                            QKV_N * DD / 4);
    round_f16_kernel<<<(DD * INNER / 4 + 255) / 256, 256>>>(w_out, woh,
                                                            DD * INNER / 4);

    // 1) QKV projection: Q,K -> bf16 split (qh/ql); V -> transposed VT bufs
    f16_gemm<true><<<dim3(QKV_N / 128, M1 / 128), 256, BGEMM_SMEM>>>(
        xh, xl, wqh, nullptr, nullptr, qh, ql, vth, vtl, M1, QKV_N, DD);

    // 2) Attention (bf16 3-term, KV double-buffered) -> fp16 split output
    attn_kernel<<<dim3(BB * HH, LL / 128), 256, AT_SMEM_BYTES>>>(
        qh, ql, vth, vtl, ah, al);

    // 3) Output projection (fp16 2-term) + bias -> d_out
    f16_gemm<false><<<dim3(INNER / 128, M1 / 128), 256, BGEMM_SMEM>>>(
        ah, al, woh, b_out, out, nullptr, nullptr, nullptr, nullptr,
        M1, DD, INNER);

    // 4) LayerNorm in-place
    ln_kernel<<<M1, 256>>>(out, gamma, beta);
}

// round 13
// speedup vs baseline: 1.3087x; 1.3087x over previous
#include <cuda_runtime.h>
#include <cstdint>
#include <cstddef>

// Problem constants
#define BB 4
#define LL 1024
#define DD 1024
#define HH 16
#define INNER 1024          // H*HD
#define M1 4096             // B*L
#define QKV_N 3072          // 3*INNER

// Scratch (static device allocations — allowed)
__device__ uint16_t g_xh[(size_t)M1 * DD];      // x split (fp16 hi)
__device__ uint16_t g_xl[(size_t)M1 * DD];      // x split (fp16 lo)
__device__ uint16_t g_wqh[(size_t)QKV_N * DD];  // w_qkv fp16 (1-term)
__device__ uint16_t g_woh[(size_t)DD * INNER];  // w_out fp16 (1-term)
__device__ uint16_t g_qh[(size_t)M1 * QKV_N];   // qkv fp16 (1-term; Q,K used)
__device__ uint16_t g_vth[(size_t)HH * 64 * BB * LL];  // V^T fp16 [e][b][l]
__device__ uint16_t g_ah[(size_t)M1 * INNER];   // attention out (fp16 hi)
__device__ uint16_t g_al[(size_t)M1 * INNER];   // attention out (fp16 lo)

// ===========================================================================
// Portable PTX helpers
// ===========================================================================
__device__ __forceinline__ uint32_t smem_u32(const void* p) {
    uint32_t a;
    asm("{ .reg .u64 t; cvta.to.shared.u64 t, %1; cvt.u32.u64 %0, t; }"
        : "=r"(a) : "l"(p));
    return a;
}
__device__ __forceinline__ void cp_async16(uint32_t dst, const void* src) {
    asm volatile("cp.async.cg.shared.global [%0], [%1], 16;"
                 :: "r"(dst), "l"(src) : "memory");
}
#define CP_COMMIT() asm volatile("cp.async.commit_group;" ::: "memory")
#define CP_WAIT(n)  asm volatile("cp.async.wait_group %0;" :: "n"(n) : "memory")

__device__ __forceinline__ void ldsm_x4(uint32_t* r, uint32_t addr) {
    asm volatile("ldmatrix.sync.aligned.m8n8.x4.shared.b16 {%0,%1,%2,%3}, [%4];"
                 : "=r"(r[0]), "=r"(r[1]), "=r"(r[2]), "=r"(r[3]) : "r"(addr));
}
__device__ __forceinline__ void mma_f16(float* d, const uint32_t* a,
                                        const uint32_t* b) {
    asm volatile(
        "mma.sync.aligned.m16n8k16.row.col.f32.f16.f16.f32 "
        "{%0,%1,%2,%3}, {%4,%5,%6,%7}, {%8,%9}, {%0,%1,%2,%3};"
        : "+f"(d[0]), "+f"(d[1]), "+f"(d[2]), "+f"(d[3])
        : "r"(a[0]), "r"(a[1]), "r"(a[2]), "r"(a[3]), "r"(b[0]), "r"(b[1]));
}
// ---- fp16 pack ----
__device__ __forceinline__ uint32_t cvt2f16(float e, float o) {
    uint32_t r;
    asm("cvt.rn.f16x2.f32 %0, %1, %2;" : "=r"(r) : "f"(o), "f"(e));
    return r;
}
__device__ __forceinline__ float f16lo2f(uint32_t h) {
    float f;
    asm("{ .reg .f16 a, b; mov.b32 {a, b}, %1; cvt.f32.f16 %0, a; }"
        : "=f"(f) : "r"(h));
    return f;
}
__device__ __forceinline__ float f16hi2f(uint32_t h) {
    float f;
    asm("{ .reg .f16 a, b; mov.b32 {a, b}, %1; cvt.f32.f16 %0, b; }"
        : "=f"(f) : "r"(h));
    return f;
}
__device__ __forceinline__ void pack_pair_f16(float e, float o,
                                              uint32_t& hi, uint32_t& lo) {
    uint32_t h = cvt2f16(e, o);
    float re = e - f16lo2f(h);
    float ro = o - f16hi2f(h);
    hi = h;
    lo = cvt2f16(re, ro);
}
__device__ __forceinline__ float fast_ex2(float x) {
    float r;
    asm("ex2.approx.ftz.f32 %0, %1;" : "=f"(r) : "f"(x));
    return r;
}

// ===========================================================================
// Split / round kernels (memory-bound)
// ===========================================================================
__global__ __launch_bounds__(256) void split_f16_kernel(
    const float* __restrict__ src, uint16_t* __restrict__ hi,
    uint16_t* __restrict__ lo, int n4)
{
    int idx = blockIdx.x * blockDim.x + threadIdx.x;
    if (idx >= n4) return;
    float4 v = ((const float4*)src)[idx];
    uint32_t h0, l0, h1, l1;
    pack_pair_f16(v.x, v.y, h0, l0);
    pack_pair_f16(v.z, v.w, h1, l1);
    ((uint2*)hi)[idx] = make_uint2(h0, h1);
    ((uint2*)lo)[idx] = make_uint2(l0, l1);
}
__global__ __launch_bounds__(256) void round_f16_kernel(
    const float* __restrict__ src, uint16_t* __restrict__ dst, int n4)
{
    int idx = blockIdx.x * blockDim.x + threadIdx.x;
    if (idx >= n4) return;
    float4 v = ((const float4*)src)[idx];
    ((uint2*)dst)[idx] = make_uint2(cvt2f16(v.x, v.y), cvt2f16(v.z, v.w));
}

// ===========================================================================
// FP16 2-term GEMM (NT): C = (Ah+Al) Bh^T. 128x128x32, 8 warps 2Mx4N.
// TWO-stage pipeline (round-11 proven). Single barrier per chunk.
// SPLIT_OUT: Q,K cols -> 1-term fp16 qkv; V cols (n0>=2048) -> transposed
// fp16 VT [e][b*1024+l] via smem transpose.
// ===========================================================================
#define BSTR 40
#define BTILE_B (128 * BSTR * 2)       // 10240 bytes
#define BGEMM_SMEM (6 * BTILE_B)       // 61440
#define TSTR 136                        // transpose tile stride (elems)

template <bool SPLIT_OUT>
__global__ __launch_bounds__(256) void f16_gemm(
    const uint16_t* __restrict__ Ah, const uint16_t* __restrict__ Al,
    const uint16_t* __restrict__ Bh,
    const float* __restrict__ bias, float* __restrict__ C,
    uint16_t* __restrict__ outH,
    uint16_t* __restrict__ vtH,
    int M, int N, int K)
{
    extern __shared__ char smraw[];
    const uint32_t sb = smem_u32(smraw);
    const int tid  = threadIdx.x;
    const int wid  = tid >> 5, lane = tid & 31;
    const int m0   = blockIdx.y << 7, n0 = blockIdx.x << 7;
    const int wm   = (wid & 1) << 6;
    const int wn   = (wid >> 1) << 5;

    uint32_t stg[2] = { sb, sb + 3 * BTILE_B };

    const int lrow = tid >> 2;
    const int lc   = tid & 3;
    const uint32_t so0 = (uint32_t)(lrow * BSTR * 2 + lc * 16);
    const uint32_t so1 = (uint32_t)((lrow + 64) * BSTR * 2 + lc * 16);
    const uint16_t* gAh = Ah + (size_t)(m0 + lrow) * K + lc * 8;
    const uint16_t* gAl = Al + (size_t)(m0 + lrow) * K + lc * 8;
    const uint16_t* gBh = Bh + (size_t)(n0 + lrow) * K + lc * 8;
    const size_t r64 = (size_t)64 * K;

    float acc[4][4][4];
#pragma unroll
    for (int i = 0; i < 4; i++)
#pragma unroll
        for (int j = 0; j < 4; j++)
#pragma unroll
            for (int k = 0; k < 4; k++) acc[i][j][k] = 0.f;

    const uint32_t arow = (uint32_t)(wm + (lane & 15));
    const uint32_t acol = (uint32_t)((lane >> 4) << 3);
    const uint32_t brow = (uint32_t)(wn + (lane & 7) + ((lane >> 4) & 1) * 8);
    const uint32_t bcol = (uint32_t)(((lane >> 3) & 1) << 3);

    const int NCH = K >> 5;

    // prologue: chunk 0 -> stage 0
    {
        uint32_t d = stg[0];
        cp_async16(d + 0 * BTILE_B + so0, gAh);
        cp_async16(d + 0 * BTILE_B + so1, gAh + r64);
        cp_async16(d + 1 * BTILE_B + so0, gAl);
        cp_async16(d + 1 * BTILE_B + so1, gAl + r64);
        cp_async16(d + 2 * BTILE_B + so0, gBh);
        cp_async16(d + 2 * BTILE_B + so1, gBh + r64);
    }
    CP_COMMIT();

    for (int ch = 0; ch < NCH; ch++) {
        const int s = ch & 1;
        CP_WAIT(0);
        __syncthreads();   // chunk ch visible; prior reads of stg[1-s] done
        if (ch + 1 < NCH) {
            const int k0 = (ch + 1) << 5;
            uint32_t d = stg[1 - s];
            cp_async16(d + 0 * BTILE_B + so0, gAh + k0);
            cp_async16(d + 0 * BTILE_B + so1, gAh + r64 + k0);
            cp_async16(d + 1 * BTILE_B + so0, gAl + k0);
            cp_async16(d + 1 * BTILE_B + so1, gAl + r64 + k0);
            cp_async16(d + 2 * BTILE_B + so0, gBh + k0);
            cp_async16(d + 2 * BTILE_B + so1, gBh + r64 + k0);
            CP_COMMIT();
        }

        const uint32_t AHB = stg[s], ALB = stg[s] + BTILE_B;
        const uint32_t BHB = stg[s] + 2 * BTILE_B;

#pragma unroll
        for (int ks = 0; ks < 2; ks++) {
            const uint32_t kadd = (uint32_t)(ks * 32);   // bytes
            uint32_t bh_[2][4];
#pragma unroll
            for (int j = 0; j < 2; j++)
                ldsm_x4(bh_[j], BHB + ((brow + j * 16) * BSTR + bcol) * 2 + kadd);
#pragma unroll
            for (int mip = 0; mip < 2; mip++) {
                const uint32_t off0 = ((arow + (2 * mip) * 16) * BSTR + acol) * 2 + kadd;
                const uint32_t off1 = ((arow + (2 * mip + 1) * 16) * BSTR + acol) * 2 + kadd;
                uint32_t ah0[4], ah1[4], al0[4], al1[4];
                ldsm_x4(ah0, AHB + off0);
                ldsm_x4(ah1, AHB + off1);
                ldsm_x4(al0, ALB + off0);
                ldsm_x4(al1, ALB + off1);
#pragma unroll
                for (int nj = 0; nj < 4; nj++)
                    mma_f16(acc[2 * mip][nj],     ah0, bh_[nj >> 1] + (nj & 1) * 2);
#pragma unroll
                for (int nj = 0; nj < 4; nj++)
                    mma_f16(acc[2 * mip + 1][nj], ah1, bh_[nj >> 1] + (nj & 1) * 2);
#pragma unroll
                for (int nj = 0; nj < 4; nj++)
                    mma_f16(acc[2 * mip][nj],     al0, bh_[nj >> 1] + (nj & 1) * 2);
#pragma unroll
                for (int nj = 0; nj < 4; nj++)
                    mma_f16(acc[2 * mip + 1][nj], al1, bh_[nj >> 1] + (nj & 1) * 2);
            }
        }
    }

    const int rbase = m0 + wm + (lane >> 2);
    const int cbase = n0 + wn + ((lane & 3) << 1);

    if (SPLIT_OUT && n0 >= 2 * INNER) {
        // ---- V columns: transpose via smem (1 pass), store fp16 VT ----
        uint16_t* T = (uint16_t*)smraw;
        const int b  = m0 >> 10;
        const int l0 = m0 & 1023;
        __syncthreads();   // mainloop reads done
        const int rloc = wm + (lane >> 2);
        const int cloc = wn + ((lane & 3) << 1);
#pragma unroll
        for (int nj = 0; nj < 4; nj++) {
#pragma unroll
            for (int mi = 0; mi < 4; mi++) {
                uint32_t w0 = cvt2f16(acc[mi][nj][0], acc[mi][nj][1]);
                uint32_t w1 = cvt2f16(acc[mi][nj][2], acc[mi][nj][3]);
                int c = cloc + nj * 8;
                int r = rloc + mi * 16;
                T[c * TSTR + r]           = (uint16_t)(w0 & 0xffffu);
                T[(c + 1) * TSTR + r]     = (uint16_t)(w0 >> 16);
                T[c * TSTR + r + 8]       = (uint16_t)(w1 & 0xffffu);
                T[(c + 1) * TSTR + r + 8] = (uint16_t)(w1 >> 16);
            }
        }
        __syncthreads();
        // Drain FULL tile: 128 cols x 16 8-row units.
#pragma unroll
        for (int i = 0; i < 8; i++) {
            int idx = tid + (i << 8);
            int c = idx >> 4, u = idx & 15;
            int e = n0 - 2 * INNER + c;
            size_t dst = ((size_t)e * BB + b) * LL + l0 + u * 8;
            *(uint4*)(vtH + dst) = *(const uint4*)(T + c * TSTR + u * 8);
        }
    } else {
#pragma unroll
        for (int nj = 0; nj < 4; nj++) {
            const int col = cbase + nj * 8;
            if (SPLIT_OUT) {
#pragma unroll
                for (int mi = 0; mi < 4; mi++) {
                    const int r0 = rbase + mi * 16;
                    uint32_t h0 = cvt2f16(acc[mi][nj][0], acc[mi][nj][1]);
                    uint32_t h1 = cvt2f16(acc[mi][nj][2], acc[mi][nj][3]);
                    *(uint32_t*)(outH + (size_t)r0 * N + col) = h0;
                    *(uint32_t*)(outH + (size_t)(r0 + 8) * N + col) = h1;
                }
            } else {
                float b0 = bias[col], b1 = bias[col + 1];
#pragma unroll
                for (int mi = 0; mi < 4; mi++) {
                    const int r0 = rbase + mi * 16;
                    float2 v0 = { acc[mi][nj][0] + b0, acc[mi][nj][1] + b1 };
                    float2 v1 = { acc[mi][nj][2] + b0, acc[mi][nj][3] + b1 };
                    *(float2*)(C + (size_t)r0 * N + col) = v0;
                    *(float2*)(C + (size_t)(r0 + 8) * N + col) = v1;
                }
            }
        }
    }
}

// ===========================================================================
// Tensor-core attention, 1-term fp16 operands (2^-11, = validated tf32
// precision of round 4). V pre-transposed (fp16 VT). Round-11 plain-load
// sync structure. Softmax exponent shifted by -8 so unnormalized p fits fp16
// (shift-invariant; row sums kept in fp32 from fp32 p).
// ===========================================================================
#define AT_STR 72
#define AQ 0
#define AK (128 * AT_STR)
#define AV (192 * AT_STR)
#define AT_ELEMS (256 * AT_STR)
#define AT_SMEM_BYTES (AT_ELEMS * 2)    // 36864 bytes

__global__ __launch_bounds__(256) void attn_kernel(
    const uint16_t* __restrict__ qh,
    const uint16_t* __restrict__ vth,
    uint16_t* __restrict__ oh, uint16_t* __restrict__ ol)
{
    extern __shared__ uint16_t sm16[];
    const uint32_t sb = smem_u32(sm16);
    const int tid = threadIdx.x, wid = tid >> 5, lane = tid & 31;
    const int bh = blockIdx.x, b = bh >> 4, h = bh & 15;
    const int q0 = blockIdx.y << 7;
    const size_t rowbase = (size_t)b * LL;

    // ---- Q tile: 128 rows x 64 cols fp16 ----
#pragma unroll
    for (int i = 0; i < 4; i++) {
        int idx = tid + (i << 8);
        if (idx < 1024) {
            int r = idx >> 3, c8 = idx & 7;
            size_t g = (rowbase + q0 + r) * QKV_N + h * 64 + c8 * 8;
            *(uint4*)(sm16 + AQ + r * AT_STR + c8 * 8) = *(const uint4*)(qh + g);
        }
    }
    __syncthreads();

    // ---- Q fragments (fp16 A-frags), reused all tiles ----
    uint32_t qf[4][4];
    {
        const uint32_t qrow = (uint32_t)((wid << 4) + (lane & 15));
        const uint32_t cc = (uint32_t)((lane >> 4) << 3);
#pragma unroll
        for (int ks = 0; ks < 4; ks++) {
            uint32_t off = (uint32_t)(qrow * AT_STR + ks * 16 + cc) * 2;
            ldsm_x4(qf[ks], sb + AQ * 2 + off);
        }
    }

    float oacc[8][4];
#pragma unroll
    for (int i = 0; i < 8; i++)
#pragma unroll
        for (int j = 0; j < 4; j++) oacc[i][j] = 0.f;
    float ls0 = 0.f, ls1 = 0.f;

    const float CE = 0.125f * 1.4426950408889634f;
    const uint32_t KB = sb + AK * 2, VBa = sb + AV * 2;

    for (int kt = 0; kt < 16; kt++) {
        __syncthreads();   // previous tile's reads done

        // K tile (rows = key j) and V^T tile (rows = d), fp16
#pragma unroll
        for (int i = 0; i < 2; i++) {
            int idx = tid + (i << 8);
            int r = idx >> 3, c8 = idx & 7;
            size_t gk = (rowbase + kt * 64 + r) * QKV_N + INNER
                        + h * 64 + c8 * 8;
            size_t gv = ((size_t)(h * 64 + r) * BB + b) * LL + kt * 64 + c8 * 8;
            *(uint4*)(sm16 + AK + r * AT_STR + c8 * 8) = *(const uint4*)(qh + gk);
            *(uint4*)(sm16 + AV + r * AT_STR + c8 * 8) = *(const uint4*)(vth + gv);
        }
        __syncthreads();

        // ---- S = Q K^T (1-term fp16) ----
        float p[8][4];
#pragma unroll
        for (int i = 0; i < 8; i++)
#pragma unroll
            for (int j = 0; j < 4; j++) p[i][j] = 0.f;

#pragma unroll
        for (int ks = 0; ks < 4; ks++) {
#pragma unroll
            for (int njp = 0; njp < 4; njp++) {
                uint32_t kf[4];
                uint32_t roff = (uint32_t)(njp * 16 + (lane & 7)
                                           + ((lane >> 4) & 1) * 8);
                uint32_t coff = (uint32_t)(ks * 16 + ((lane >> 3) & 1) * 8);
                ldsm_x4(kf, KB + (roff * AT_STR + coff) * 2);
                mma_f16(p[2 * njp],     qf[ks], kf);
                mma_f16(p[2 * njp + 1], qf[ks], kf + 2);
            }
        }

        // ---- exp (clamped, exponent shifted -8 for fp16 range) ----
#pragma unroll
        for (int nt = 0; nt < 8; nt++) {
#pragma unroll
            for (int q = 0; q < 4; q++) {
                float a_ = fminf(p[nt][q] * CE, 80.f) - 8.f;
                p[nt][q] = fast_ex2(a_);
            }
            ls0 += p[nt][0] + p[nt][1];
            ls1 += p[nt][2] + p[nt][3];
        }

        // ---- repack P -> fp16 A-frags ----
        uint32_t pa[4][4];
#pragma unroll
        for (int ks = 0; ks < 4; ks++) {
            pa[ks][0] = cvt2f16(p[2 * ks][0],     p[2 * ks][1]);
            pa[ks][1] = cvt2f16(p[2 * ks][2],     p[2 * ks][3]);
            pa[ks][2] = cvt2f16(p[2 * ks + 1][0], p[2 * ks + 1][1]);
            pa[ks][3] = cvt2f16(p[2 * ks + 1][2], p[2 * ks + 1][3]);
        }

        // ---- O += P V (1-term fp16) ----
#pragma unroll
        for (int ks = 0; ks < 4; ks++) {
#pragma unroll
            for (int dtp = 0; dtp < 4; dtp++) {
                uint32_t vf[4];
                uint32_t roff = (uint32_t)(dtp * 16 + (lane & 7)
                                           + ((lane >> 4) & 1) * 8);
                uint32_t coff = (uint32_t)(ks * 16 + ((lane >> 3) & 1) * 8);
                ldsm_x4(vf, VBa + (roff * AT_STR + coff) * 2);
                mma_f16(oacc[2 * dtp],     pa[ks], vf);
                mma_f16(oacc[2 * dtp + 1], pa[ks], vf + 2);
            }
        }
    }

    // ---- epilogue: normalize + fp16 2-term split-store ----
    ls0 += __shfl_xor_sync(0xffffffffu, ls0, 1);
    ls0 += __shfl_xor_sync(0xffffffffu, ls0, 2);
    ls1 += __shfl_xor_sync(0xffffffffu, ls1, 1);
    ls1 += __shfl_xor_sync(0xffffffffu, ls1, 2);
    const float i0 = 1.f / fmaxf(ls0, 1e-30f);
    const float i1 = 1.f / fmaxf(ls1, 1e-30f);

    const int r0 = q0 + (wid << 4) + (lane >> 2);
    const int col = h * 64 + ((lane & 3) << 1);
#pragma unroll
    for (int dt = 0; dt < 8; dt++) {
        uint32_t h0, l0, h1, l1;
        pack_pair_f16(oacc[dt][0] * i0, oacc[dt][1] * i0, h0, l0);
        pack_pair_f16(oacc[dt][2] * i1, oacc[dt][3] * i1, h1, l1);
        size_t g0 = (rowbase + r0) * INNER + col + dt * 8;
        size_t g1 = (rowbase + r0 + 8) * INNER + col + dt * 8;
        *(uint32_t*)(oh + g0) = h0;
        *(uint32_t*)(ol + g0) = l0;
        *(uint32_t*)(oh + g1) = h1;
        *(uint32_t*)(ol + g1) = l1;
    }
}

// ---------------------------------------------------------------------------
// In-place LayerNorm (biased variance), one 256-thread block per row.
// ---------------------------------------------------------------------------
__global__ __launch_bounds__(256) void ln_kernel(
    float* __restrict__ Y, const float* __restrict__ gamma,
    const float* __restrict__ beta)
{
    const int row = blockIdx.x;
    float* y = Y + (size_t)row * DD;
    const int tid = threadIdx.x;

    float v[4];
    float s = 0.f, ss = 0.f;
#pragma unroll
    for (int i = 0; i < 4; i++) {
        v[i] = y[tid + (i << 8)];
        s += v[i];
        ss += v[i] * v[i];
    }
#pragma unroll
    for (int o = 16; o; o >>= 1) {
        s  += __shfl_xor_sync(0xffffffffu, s, o);
        ss += __shfl_xor_sync(0xffffffffu, ss, o);
    }
    __shared__ float rs[8], rss[8], mv[2];
    int w = tid >> 5, lane = tid & 31;
    if (!lane) { rs[w] = s; rss[w] = ss; }
    __syncthreads();
    if (tid == 0) {
        float S = 0.f, SS = 0.f;
#pragma unroll
        for (int i = 0; i < 8; i++) { S += rs[i]; SS += rss[i]; }
        float mean = S * (1.f / 1024.f);
        float var  = SS * (1.f / 1024.f) - mean * mean;
        mv[0] = mean;
        mv[1] = rsqrtf(var + 1e-5f);
    }
    __syncthreads();
    float mean = mv[0], rstd = mv[1];
#pragma unroll
    for (int i = 0; i < 4; i++) {
        int d = tid + (i << 8);
        y[d] = (v[i] - mean) * rstd * gamma[d] + beta[d];
    }
}

// ---------------------------------------------------------------------------
// Launch
// ---------------------------------------------------------------------------
extern "C" void kernel_launch(void* const* d_in, const int* in_sizes, int n_in,
                              void* d_out, int out_size)
{
    const float* x     = (const float*)d_in[0];
    const float* w_qkv = (const float*)d_in[2];
    const float* w_out = (const float*)d_in[3];
    const float* b_out = (const float*)d_in[4];
    const float* gamma = (const float*)d_in[5];
    const float* beta  = (const float*)d_in[6];
    float* out = (float*)d_out;

    uint16_t *xh, *xl, *wqh, *woh, *qh, *vth, *ah, *al;
    cudaGetSymbolAddress((void**)&xh,  g_xh);
    cudaGetSymbolAddress((void**)&xl,  g_xl);
    cudaGetSymbolAddress((void**)&wqh, g_wqh);
    cudaGetSymbolAddress((void**)&woh, g_woh);
    cudaGetSymbolAddress((void**)&qh,  g_qh);
    cudaGetSymbolAddress((void**)&vth, g_vth);
    cudaGetSymbolAddress((void**)&ah,  g_ah);
    cudaGetSymbolAddress((void**)&al,  g_al);

    cudaFuncSetAttribute(f16_gemm<true>,
                         cudaFuncAttributeMaxDynamicSharedMemorySize,
                         BGEMM_SMEM);
    cudaFuncSetAttribute(f16_gemm<false>,
                         cudaFuncAttributeMaxDynamicSharedMemorySize,
                         BGEMM_SMEM);
    cudaFuncSetAttribute(attn_kernel,
                         cudaFuncAttributeMaxDynamicSharedMemorySize,
                         AT_SMEM_BYTES);

    // 0) Split x (fp16 2-term); round weights (fp16 1-term)
    split_f16_kernel<<<(M1 * DD / 4 + 255) / 256, 256>>>(x, xh, xl, M1 * DD / 4);
    round_f16_kernel<<<(QKV_N * DD / 4 + 255) / 256, 256>>>(w_qkv, wqh,
                                                            QKV_N * DD / 4);
    round_f16_kernel<<<(DD * INNER / 4 + 255) / 256, 256>>>(w_out, woh,
                                                            DD * INNER / 4);

    // 1) QKV projection: Q,K -> fp16 qkv; V -> transposed fp16 VT
    f16_gemm<true><<<dim3(QKV_N / 128, M1 / 128), 256, BGEMM_SMEM>>>(
        xh, xl, wqh, nullptr, nullptr, qh, vth, M1, QKV_N, DD);

    // 2) Attention (1-term fp16 MMA) -> fp16 2-term split output
    attn_kernel<<<dim3(BB * HH, LL / 128), 256, AT_SMEM_BYTES>>>(
        qh, vth, ah, al);

    // 3) Output projection (fp16 2-term A) + bias -> d_out
    f16_gemm<false><<<dim3(INNER / 128, M1 / 128), 256, BGEMM_SMEM>>>(
        ah, al, woh, b_out, out, nullptr, nullptr, M1, DD, INNER);

    // 4) LayerNorm in-place
    ln_kernel<<<M1, 256>>>(out, gamma, beta);
}

// round 14
// speedup vs baseline: 1.4685x; 1.1221x over previous
#include <cuda_runtime.h>
#include <cstdint>
#include <cstddef>

// Problem constants
#define BB 4
#define LL 1024
#define DD 1024
#define HH 16
#define INNER 1024          // H*HD
#define M1 4096             // B*L
#define QKV_N 3072          // 3*INNER

// Scratch (static device allocations — allowed)
__device__ uint16_t g_xh[(size_t)M1 * DD];      // x split (fp16 hi)
__device__ uint16_t g_xl[(size_t)M1 * DD];      // x split (fp16 lo)
__device__ uint16_t g_wqh[(size_t)QKV_N * DD];  // w_qkv fp16 (1-term)
__device__ uint16_t g_woh[(size_t)DD * INNER];  // w_out fp16 (1-term)
__device__ uint16_t g_qh[(size_t)M1 * QKV_N];   // qkv fp16 (1-term; Q,K used)
__device__ uint16_t g_vth[(size_t)HH * 64 * BB * LL];  // V^T fp16 [e][b][l]
__device__ uint16_t g_ah[(size_t)M1 * INNER];   // attention out (fp16 hi)
__device__ uint16_t g_al[(size_t)M1 * INNER];   // attention out (fp16 lo)

// ===========================================================================
// Portable PTX helpers
// ===========================================================================
__device__ __forceinline__ uint32_t smem_u32(const void* p) {
    uint32_t a;
    asm("{ .reg .u64 t; cvta.to.shared.u64 t, %1; cvt.u32.u64 %0, t; }"
        : "=r"(a) : "l"(p));
    return a;
}
__device__ __forceinline__ void cp_async16(uint32_t dst, const void* src) {
    asm volatile("cp.async.cg.shared.global [%0], [%1], 16;"
                 :: "r"(dst), "l"(src) : "memory");
}
#define CP_COMMIT() asm volatile("cp.async.commit_group;" ::: "memory")
#define CP_WAIT(n)  asm volatile("cp.async.wait_group %0;" :: "n"(n) : "memory")

__device__ __forceinline__ void ldsm_x4(uint32_t* r, uint32_t addr) {
    asm volatile("ldmatrix.sync.aligned.m8n8.x4.shared.b16 {%0,%1,%2,%3}, [%4];"
                 : "=r"(r[0]), "=r"(r[1]), "=r"(r[2]), "=r"(r[3]) : "r"(addr));
}
__device__ __forceinline__ void mma_f16(float* d, const uint32_t* a,
                                        const uint32_t* b) {
    asm volatile(
        "mma.sync.aligned.m16n8k16.row.col.f32.f16.f16.f32 "
        "{%0,%1,%2,%3}, {%4,%5,%6,%7}, {%8,%9}, {%0,%1,%2,%3};"
        : "+f"(d[0]), "+f"(d[1]), "+f"(d[2]), "+f"(d[3])
        : "r"(a[0]), "r"(a[1]), "r"(a[2]), "r"(a[3]), "r"(b[0]), "r"(b[1]));
}
// ---- fp16 pack ----
__device__ __forceinline__ uint32_t cvt2f16(float e, float o) {
    uint32_t r;
    asm("cvt.rn.f16x2.f32 %0, %1, %2;" : "=r"(r) : "f"(o), "f"(e));
    return r;
}
__device__ __forceinline__ float f16lo2f(uint32_t h) {
    float f;
    asm("{ .reg .f16 a, b; mov.b32 {a, b}, %1; cvt.f32.f16 %0, a; }"
        : "=f"(f) : "r"(h));
    return f;
}
__device__ __forceinline__ float f16hi2f(uint32_t h) {
    float f;
    asm("{ .reg .f16 a, b; mov.b32 {a, b}, %1; cvt.f32.f16 %0, b; }"
        : "=f"(f) : "r"(h));
    return f;
}
__device__ __forceinline__ void pack_pair_f16(float e, float o,
                                              uint32_t& hi, uint32_t& lo) {
    uint32_t h = cvt2f16(e, o);
    float re = e - f16lo2f(h);
    float ro = o - f16hi2f(h);
    hi = h;
    lo = cvt2f16(re, ro);
}
__device__ __forceinline__ float fast_ex2(float x) {
    float r;
    asm("ex2.approx.ftz.f32 %0, %1;" : "=f"(r) : "f"(x));
    return r;
}

// ===========================================================================
// Split / round kernels (memory-bound)
// ===========================================================================
__global__ __launch_bounds__(256) void split_f16_kernel(
    const float* __restrict__ src, uint16_t* __restrict__ hi,
    uint16_t* __restrict__ lo, int n4)
{
    int idx = blockIdx.x * blockDim.x + threadIdx.x;
    if (idx >= n4) return;
    float4 v = ((const float4*)src)[idx];
    uint32_t h0, l0, h1, l1;
    pack_pair_f16(v.x, v.y, h0, l0);
    pack_pair_f16(v.z, v.w, h1, l1);
    ((uint2*)hi)[idx] = make_uint2(h0, h1);
    ((uint2*)lo)[idx] = make_uint2(l0, l1);
}
__global__ __launch_bounds__(256) void round_f16_kernel(
    const float* __restrict__ src, uint16_t* __restrict__ dst, int n4)
{
    int idx = blockIdx.x * blockDim.x + threadIdx.x;
    if (idx >= n4) return;
    float4 v = ((const float4*)src)[idx];
    ((uint2*)dst)[idx] = make_uint2(cvt2f16(v.x, v.y), cvt2f16(v.z, v.w));
}

// ===========================================================================
// FP16 2-term GEMM (NT): C = (Ah+Al) Bh^T. 128x128 tile, K-chunks of 64
// (halves barrier/wait count vs 32). 8 warps 2Mx4N. 2-stage pipeline.
// SPLIT_OUT: Q,K cols -> 1-term fp16 qkv; V cols (n0>=2048) -> transposed
// fp16 VT [e][b*1024+l] via smem transpose.
// ===========================================================================
#define BSTR 72                         // smem row stride (elems) = 144 B
#define MTILE_B (128 * BSTR * 2)        // 18432 bytes per matrix tile
#define BGEMM_SMEM (6 * MTILE_B)        // 2 stages x (Ah,Al,Bh) = 110592
#define TSTR 136                         // transpose tile stride (elems)

template <bool SPLIT_OUT>
__global__ __launch_bounds__(256) void f16_gemm(
    const uint16_t* __restrict__ Ah, const uint16_t* __restrict__ Al,
    const uint16_t* __restrict__ Bh,
    const float* __restrict__ bias, float* __restrict__ C,
    uint16_t* __restrict__ outH,
    uint16_t* __restrict__ vtH,
    int M, int N, int K)
{
    extern __shared__ char smraw[];
    const uint32_t sb = smem_u32(smraw);
    const int tid  = threadIdx.x;
    const int wid  = tid >> 5, lane = tid & 31;
    const int m0   = blockIdx.y << 7, n0 = blockIdx.x << 7;
    const int wm   = (wid & 1) << 6;
    const int wn   = (wid >> 1) << 5;

    uint32_t stg[2] = { sb, sb + 3 * MTILE_B };

    // loads: 128 rows x 8 16B-units per matrix -> 4 units per thread
    int lrw[4]; uint32_t so[4];
#pragma unroll
    for (int i = 0; i < 4; i++) {
        int idx = tid + (i << 8);
        int row = idx >> 3, c8 = idx & 7;
        lrw[i] = row;
        so[i] = (uint32_t)(row * BSTR + c8 * 8) * 2;
    }
    const int lco = (tid & 7) * 8;   // element column of this thread's units
    const uint16_t* gAh = Ah + (size_t)m0 * K + lco;
    const uint16_t* gAl = Al + (size_t)m0 * K + lco;
    const uint16_t* gBh = Bh + (size_t)n0 * K + lco;

    float acc[4][4][4];
#pragma unroll
    for (int i = 0; i < 4; i++)
#pragma unroll
        for (int j = 0; j < 4; j++)
#pragma unroll
            for (int k = 0; k < 4; k++) acc[i][j][k] = 0.f;

    const uint32_t arow = (uint32_t)(wm + (lane & 15));
    const uint32_t acol = (uint32_t)((lane >> 4) << 3);
    const uint32_t brow = (uint32_t)(wn + (lane & 7) + ((lane >> 4) & 1) * 8);
    const uint32_t bcol = (uint32_t)(((lane >> 3) & 1) << 3);

    const int NCH = K >> 6;             // 64-wide chunks

    // prologue: chunk 0 -> stage 0
    {
        uint32_t d = stg[0];
#pragma unroll
        for (int i = 0; i < 4; i++) {
            size_t g = (size_t)lrw[i] * K;
            cp_async16(d + 0 * MTILE_B + so[i], gAh + g);
            cp_async16(d + 1 * MTILE_B + so[i], gAl + g);
            cp_async16(d + 2 * MTILE_B + so[i], gBh + g);
        }
    }
    CP_COMMIT();

    for (int ch = 0; ch < NCH; ch++) {
        const int s = ch & 1;
        CP_WAIT(0);
        __syncthreads();   // chunk ch visible; prior reads of stg[1-s] done
        if (ch + 1 < NCH) {
            const int k0 = (ch + 1) << 6;
            uint32_t d = stg[1 - s];
#pragma unroll
            for (int i = 0; i < 4; i++) {
                size_t g = (size_t)lrw[i] * K + k0;
                cp_async16(d + 0 * MTILE_B + so[i], gAh + g);
                cp_async16(d + 1 * MTILE_B + so[i], gAl + g);
                cp_async16(d + 2 * MTILE_B + so[i], gBh + g);
            }
            CP_COMMIT();
        }

        const uint32_t AHB = stg[s], ALB = stg[s] + MTILE_B;
        const uint32_t BHB = stg[s] + 2 * MTILE_B;

#pragma unroll
        for (int ks = 0; ks < 4; ks++) {
            const uint32_t kadd = (uint32_t)(ks * 32);   // 16 elems = 32 bytes
            uint32_t bh_[2][4];
#pragma unroll
            for (int j = 0; j < 2; j++)
                ldsm_x4(bh_[j], BHB + ((brow + j * 16) * BSTR + bcol) * 2 + kadd);
#pragma unroll
            for (int mip = 0; mip < 2; mip++) {
                const uint32_t off0 = ((arow + (2 * mip) * 16) * BSTR + acol) * 2 + kadd;
                const uint32_t off1 = ((arow + (2 * mip + 1) * 16) * BSTR + acol) * 2 + kadd;
                uint32_t ah0[4], ah1[4], al0[4], al1[4];
                ldsm_x4(ah0, AHB + off0);
                ldsm_x4(ah1, AHB + off1);
                ldsm_x4(al0, ALB + off0);
                ldsm_x4(al1, ALB + off1);
#pragma unroll
                for (int nj = 0; nj < 4; nj++)
                    mma_f16(acc[2 * mip][nj],     ah0, bh_[nj >> 1] + (nj & 1) * 2);
#pragma unroll
                for (int nj = 0; nj < 4; nj++)
                    mma_f16(acc[2 * mip + 1][nj], ah1, bh_[nj >> 1] + (nj & 1) * 2);
#pragma unroll
                for (int nj = 0; nj < 4; nj++)
                    mma_f16(acc[2 * mip][nj],     al0, bh_[nj >> 1] + (nj & 1) * 2);
#pragma unroll
                for (int nj = 0; nj < 4; nj++)
                    mma_f16(acc[2 * mip + 1][nj], al1, bh_[nj >> 1] + (nj & 1) * 2);
            }
        }
    }

    const int rbase = m0 + wm + (lane >> 2);
    const int cbase = n0 + wn + ((lane & 3) << 1);

    if (SPLIT_OUT && n0 >= 2 * INNER) {
        // ---- V columns: transpose via smem (1 pass), store fp16 VT ----
        uint16_t* T = (uint16_t*)smraw;
        const int b  = m0 >> 10;
        const int l0 = m0 & 1023;
        __syncthreads();   // mainloop reads done
        const int rloc = wm + (lane >> 2);
        const int cloc = wn + ((lane & 3) << 1);
#pragma unroll
        for (int nj = 0; nj < 4; nj++) {
#pragma unroll
            for (int mi = 0; mi < 4; mi++) {
                uint32_t w0 = cvt2f16(acc[mi][nj][0], acc[mi][nj][1]);
                uint32_t w1 = cvt2f16(acc[mi][nj][2], acc[mi][nj][3]);
                int c = cloc + nj * 8;
                int r = rloc + mi * 16;
                T[c * TSTR + r]           = (uint16_t)(w0 & 0xffffu);
                T[(c + 1) * TSTR + r]     = (uint16_t)(w0 >> 16);
                T[c * TSTR + r + 8]       = (uint16_t)(w1 & 0xffffu);
                T[(c + 1) * TSTR + r + 8] = (uint16_t)(w1 >> 16);
            }
        }
        __syncthreads();
        // Drain FULL tile: 128 cols x 16 8-row units.
#pragma unroll
        for (int i = 0; i < 8; i++) {
            int idx = tid + (i << 8);
            int c = idx >> 4, u = idx & 15;
            int e = n0 - 2 * INNER + c;
            size_t dst = ((size_t)e * BB + b) * LL + l0 + u * 8;
            *(uint4*)(vtH + dst) = *(const uint4*)(T + c * TSTR + u * 8);
        }
    } else {
#pragma unroll
        for (int nj = 0; nj < 4; nj++) {
            const int col = cbase + nj * 8;
            if (SPLIT_OUT) {
#pragma unroll
                for (int mi = 0; mi < 4; mi++) {
                    const int r0 = rbase + mi * 16;
                    uint32_t h0 = cvt2f16(acc[mi][nj][0], acc[mi][nj][1]);
                    uint32_t h1 = cvt2f16(acc[mi][nj][2], acc[mi][nj][3]);
                    *(uint32_t*)(outH + (size_t)r0 * N + col) = h0;
                    *(uint32_t*)(outH + (size_t)(r0 + 8) * N + col) = h1;
                }
            } else {
                float b0 = bias[col], b1 = bias[col + 1];
#pragma unroll
                for (int mi = 0; mi < 4; mi++) {
                    const int r0 = rbase + mi * 16;
                    float2 v0 = { acc[mi][nj][0] + b0, acc[mi][nj][1] + b1 };
                    float2 v1 = { acc[mi][nj][2] + b0, acc[mi][nj][3] + b1 };
                    *(float2*)(C + (size_t)r0 * N + col) = v0;
                    *(float2*)(C + (size_t)(r0 + 8) * N + col) = v1;
                }
            }
        }
    }
}

// ===========================================================================
// Tensor-core attention, 1-term fp16 operands (round-13 proven, unchanged).
// ===========================================================================
#define AT_STR 72
#define AQ 0
#define AK (128 * AT_STR)
#define AV (192 * AT_STR)
#define AT_ELEMS (256 * AT_STR)
#define AT_SMEM_BYTES (AT_ELEMS * 2)    // 36864 bytes

__global__ __launch_bounds__(256) void attn_kernel(
    const uint16_t* __restrict__ qh,
    const uint16_t* __restrict__ vth,
    uint16_t* __restrict__ oh, uint16_t* __restrict__ ol)
{
    extern __shared__ uint16_t sm16[];
    const uint32_t sb = smem_u32(sm16);
    const int tid = threadIdx.x, wid = tid >> 5, lane = tid & 31;
    const int bh = blockIdx.x, b = bh >> 4, h = bh & 15;
    const int q0 = blockIdx.y << 7;
    const size_t rowbase = (size_t)b * LL;

    // ---- Q tile: 128 rows x 64 cols fp16 ----
#pragma unroll
    for (int i = 0; i < 4; i++) {
        int idx = tid + (i << 8);
        if (idx < 1024) {
            int r = idx >> 3, c8 = idx & 7;
            size_t g = (rowbase + q0 + r) * QKV_N + h * 64 + c8 * 8;
            *(uint4*)(sm16 + AQ + r * AT_STR + c8 * 8) = *(const uint4*)(qh + g);
        }
    }
    __syncthreads();

    uint32_t qf[4][4];
    {
        const uint32_t qrow = (uint32_t)((wid << 4) + (lane & 15));
        const uint32_t cc = (uint32_t)((lane >> 4) << 3);
#pragma unroll
        for (int ks = 0; ks < 4; ks++) {
            uint32_t off = (uint32_t)(qrow * AT_STR + ks * 16 + cc) * 2;
            ldsm_x4(qf[ks], sb + AQ * 2 + off);
        }
    }

    float oacc[8][4];
#pragma unroll
    for (int i = 0; i < 8; i++)
#pragma unroll
        for (int j = 0; j < 4; j++) oacc[i][j] = 0.f;
    float ls0 = 0.f, ls1 = 0.f;

    const float CE = 0.125f * 1.4426950408889634f;
    const uint32_t KB = sb + AK * 2, VBa = sb + AV * 2;

    for (int kt = 0; kt < 16; kt++) {
        __syncthreads();

#pragma unroll
        for (int i = 0; i < 2; i++) {
            int idx = tid + (i << 8);
            int r = idx >> 3, c8 = idx & 7;
            size_t gk = (rowbase + kt * 64 + r) * QKV_N + INNER
                        + h * 64 + c8 * 8;
            size_t gv = ((size_t)(h * 64 + r) * BB + b) * LL + kt * 64 + c8 * 8;
            *(uint4*)(sm16 + AK + r * AT_STR + c8 * 8) = *(const uint4*)(qh + gk);
            *(uint4*)(sm16 + AV + r * AT_STR + c8 * 8) = *(const uint4*)(vth + gv);
        }
        __syncthreads();

        // ---- S = Q K^T (1-term fp16) ----
        float p[8][4];
#pragma unroll
        for (int i = 0; i < 8; i++)
#pragma unroll
            for (int j = 0; j < 4; j++) p[i][j] = 0.f;

#pragma unroll
        for (int ks = 0; ks < 4; ks++) {
#pragma unroll
            for (int njp = 0; njp < 4; njp++) {
                uint32_t kf[4];
                uint32_t roff = (uint32_t)(njp * 16 + (lane & 7)
                                           + ((lane >> 4) & 1) * 8);
                uint32_t coff = (uint32_t)(ks * 16 + ((lane >> 3) & 1) * 8);
                ldsm_x4(kf, KB + (roff * AT_STR + coff) * 2);
                mma_f16(p[2 * njp],     qf[ks], kf);
                mma_f16(p[2 * njp + 1], qf[ks], kf + 2);
            }
        }

        // ---- exp (clamped, exponent shifted -8 for fp16 range) ----
#pragma unroll
        for (int nt = 0; nt < 8; nt++) {
#pragma unroll
            for (int q = 0; q < 4; q++) {
                float a_ = fminf(p[nt][q] * CE, 80.f) - 8.f;
                p[nt][q] = fast_ex2(a_);
            }
            ls0 += p[nt][0] + p[nt][1];
            ls1 += p[nt][2] + p[nt][3];
        }

        // ---- repack P -> fp16 A-frags ----
        uint32_t pa[4][4];
#pragma unroll
        for (int ks = 0; ks < 4; ks++) {
            pa[ks][0] = cvt2f16(p[2 * ks][0],     p[2 * ks][1]);
            pa[ks][1] = cvt2f16(p[2 * ks][2],     p[2 * ks][3]);
            pa[ks][2] = cvt2f16(p[2 * ks + 1][0], p[2 * ks + 1][1]);
            pa[ks][3] = cvt2f16(p[2 * ks + 1][2], p[2 * ks + 1][3]);
        }

        // ---- O += P V (1-term fp16) ----
#pragma unroll
        for (int ks = 0; ks < 4; ks++) {
#pragma unroll
            for (int dtp = 0; dtp < 4; dtp++) {
                uint32_t vf[4];
                uint32_t roff = (uint32_t)(dtp * 16 + (lane & 7)
                                           + ((lane >> 4) & 1) * 8);
                uint32_t coff = (uint32_t)(ks * 16 + ((lane >> 3) & 1) * 8);
                ldsm_x4(vf, VBa + (roff * AT_STR + coff) * 2);
                mma_f16(oacc[2 * dtp],     pa[ks], vf);
                mma_f16(oacc[2 * dtp + 1], pa[ks], vf + 2);
            }
        }
    }

    // ---- epilogue: normalize + fp16 2-term split-store ----
    ls0 += __shfl_xor_sync(0xffffffffu, ls0, 1);
    ls0 += __shfl_xor_sync(0xffffffffu, ls0, 2);
    ls1 += __shfl_xor_sync(0xffffffffu, ls1, 1);
    ls1 += __shfl_xor_sync(0xffffffffu, ls1, 2);
    const float i0 = 1.f / fmaxf(ls0, 1e-30f);
    const float i1 = 1.f / fmaxf(ls1, 1e-30f);

    const int r0 = q0 + (wid << 4) + (lane >> 2);
    const int col = h * 64 + ((lane & 3) << 1);
#pragma unroll
    for (int dt = 0; dt < 8; dt++) {
        uint32_t h0, l0, h1, l1;
        pack_pair_f16(oacc[dt][0] * i0, oacc[dt][1] * i0, h0, l0);
        pack_pair_f16(oacc[dt][2] * i1, oacc[dt][3] * i1, h1, l1);
        size_t g0 = (rowbase + r0) * INNER + col + dt * 8;
        size_t g1 = (rowbase + r0 + 8) * INNER + col + dt * 8;
        *(uint32_t*)(oh + g0) = h0;
        *(uint32_t*)(ol + g0) = l0;
        *(uint32_t*)(oh + g1) = h1;
        *(uint32_t*)(ol + g1) = l1;
    }
}

// ---------------------------------------------------------------------------
// In-place LayerNorm (biased variance), one 256-thread block per row.
// ---------------------------------------------------------------------------
__global__ __launch_bounds__(256) void ln_kernel(
    float* __restrict__ Y, const float* __restrict__ gamma,
    const float* __restrict__ beta)
{
    const int row = blockIdx.x;
    float* y = Y + (size_t)row * DD;
    const int tid = threadIdx.x;

    float v[4];
    float s = 0.f, ss = 0.f;
#pragma unroll
    for (int i = 0; i < 4; i++) {
        v[i] = y[tid + (i << 8)];
        s += v[i];
        ss += v[i] * v[i];
    }
#pragma unroll
    for (int o = 16; o; o >>= 1) {
        s  += __shfl_xor_sync(0xffffffffu, s, o);
        ss += __shfl_xor_sync(0xffffffffu, ss, o);
    }
    __shared__ float rs[8], rss[8], mv[2];
    int w = tid >> 5, lane = tid & 31;
    if (!lane) { rs[w] = s; rss[w] = ss; }
    __syncthreads();
    if (tid == 0) {
        float S = 0.f, SS = 0.f;
#pragma unroll
        for (int i = 0; i < 8; i++) { S += rs[i]; SS += rss[i]; }
        float mean = S * (1.f / 1024.f);
        float var  = SS * (1.f / 1024.f) - mean * mean;
        mv[0] = mean;
        mv[1] = rsqrtf(var + 1e-5f);
    }
    __syncthreads();
    float mean = mv[0], rstd = mv[1];
#pragma unroll
    for (int i = 0; i < 4; i++) {
        int d = tid + (i << 8);
        y[d] = (v[i] - mean) * rstd * gamma[d] + beta[d];
    }
}

// ---------------------------------------------------------------------------
// Launch
// ---------------------------------------------------------------------------
extern "C" void kernel_launch(void* const* d_in, const int* in_sizes, int n_in,
                              void* d_out, int out_size)
{
    const float* x     = (const float*)d_in[0];
    const float* w_qkv = (const float*)d_in[2];
    const float* w_out = (const float*)d_in[3];
    const float* b_out = (const float*)d_in[4];
    const float* gamma = (const float*)d_in[5];
    const float* beta  = (const float*)d_in[6];
    float* out = (float*)d_out;

    uint16_t *xh, *xl, *wqh, *woh, *qh, *vth, *ah, *al;
    cudaGetSymbolAddress((void**)&xh,  g_xh);
    cudaGetSymbolAddress((void**)&xl,  g_xl);
    cudaGetSymbolAddress((void**)&wqh, g_wqh);
    cudaGetSymbolAddress((void**)&woh, g_woh);
    cudaGetSymbolAddress((void**)&qh,  g_qh);
    cudaGetSymbolAddress((void**)&vth, g_vth);
    cudaGetSymbolAddress((void**)&ah,  g_ah);
    cudaGetSymbolAddress((void**)&al,  g_al);

    cudaFuncSetAttribute(f16_gemm<true>,
                         cudaFuncAttributeMaxDynamicSharedMemorySize,
                         BGEMM_SMEM);
    cudaFuncSetAttribute(f16_gemm<false>,
                         cudaFuncAttributeMaxDynamicSharedMemorySize,
                         BGEMM_SMEM);
    cudaFuncSetAttribute(attn_kernel,
                         cudaFuncAttributeMaxDynamicSharedMemorySize,
                         AT_SMEM_BYTES);

    // 0) Split x (fp16 2-term); round weights (fp16 1-term)
    split_f16_kernel<<<(M1 * DD / 4 + 255) / 256, 256>>>(x, xh, xl, M1 * DD / 4);
    round_f16_kernel<<<(QKV_N * DD / 4 + 255) / 256, 256>>>(w_qkv, wqh,
                                                            QKV_N * DD / 4);
    round_f16_kernel<<<(DD * INNER / 4 + 255) / 256, 256>>>(w_out, woh,
                                                            DD * INNER / 4);

    // 1) QKV projection: Q,K -> fp16 qkv; V -> transposed fp16 VT
    f16_gemm<true><<<dim3(QKV_N / 128, M1 / 128), 256, BGEMM_SMEM>>>(
        xh, xl, wqh, nullptr, nullptr, qh, vth, M1, QKV_N, DD);

    // 2) Attention (1-term fp16 MMA) -> fp16 2-term split output
    attn_kernel<<<dim3(BB * HH, LL / 128), 256, AT_SMEM_BYTES>>>(
        qh, vth, ah, al);

    // 3) Output projection (fp16 2-term A) + bias -> d_out
    f16_gemm<false><<<dim3(INNER / 128, M1 / 128), 256, BGEMM_SMEM>>>(
        ah, al, woh, b_out, out, nullptr, nullptr, M1, DD, INNER);

    // 4) LayerNorm in-place
    ln_kernel<<<M1, 256>>>(out, gamma, beta);
}

// round 15
// speedup vs baseline: 1.8006x; 1.2262x over previous
#include <cuda_runtime.h>
#include <cstdint>
#include <cstddef>

// Problem constants
#define BB 4
#define LL 1024
#define DD 1024
#define HH 16
#define INNER 1024          // H*HD
#define M1 4096             // B*L
#define QKV_N 3072          // 3*INNER

// Scratch (static device allocations — allowed)
__device__ uint16_t g_xh[(size_t)M1 * DD];      // x fp16 (1-term)
__device__ uint16_t g_wqh[(size_t)QKV_N * DD];  // w_qkv fp16 (1-term)
__device__ uint16_t g_woh[(size_t)DD * INNER];  // w_out fp16 (1-term)
__device__ uint16_t g_qh[(size_t)M1 * QKV_N];   // qkv fp16 (Q,K used)
__device__ uint16_t g_vth[(size_t)HH * 64 * BB * LL];  // V^T fp16 [e][b][l]
__device__ uint16_t g_ah[(size_t)M1 * INNER];   // attention out (fp16 hi)
__device__ uint16_t g_al[(size_t)M1 * INNER];   // attention out (fp16 lo)

// ===========================================================================
// Portable PTX helpers
// ===========================================================================
__device__ __forceinline__ uint32_t smem_u32(const void* p) {
    uint32_t a;
    asm("{ .reg .u64 t; cvta.to.shared.u64 t, %1; cvt.u32.u64 %0, t; }"
        : "=r"(a) : "l"(p));
    return a;
}
__device__ __forceinline__ void cp_async16(uint32_t dst, const void* src) {
    asm volatile("cp.async.cg.shared.global [%0], [%1], 16;"
                 :: "r"(dst), "l"(src) : "memory");
}
#define CP_COMMIT() asm volatile("cp.async.commit_group;" ::: "memory")
#define CP_WAIT(n)  asm volatile("cp.async.wait_group %0;" :: "n"(n) : "memory")

__device__ __forceinline__ void ldsm_x4(uint32_t* r, uint32_t addr) {
    asm volatile("ldmatrix.sync.aligned.m8n8.x4.shared.b16 {%0,%1,%2,%3}, [%4];"
                 : "=r"(r[0]), "=r"(r[1]), "=r"(r[2]), "=r"(r[3]) : "r"(addr));
}
__device__ __forceinline__ void mma_f16(float* d, const uint32_t* a,
                                        const uint32_t* b) {
    asm volatile(
        "mma.sync.aligned.m16n8k16.row.col.f32.f16.f16.f32 "
        "{%0,%1,%2,%3}, {%4,%5,%6,%7}, {%8,%9}, {%0,%1,%2,%3};"
        : "+f"(d[0]), "+f"(d[1]), "+f"(d[2]), "+f"(d[3])
        : "r"(a[0]), "r"(a[1]), "r"(a[2]), "r"(a[3]), "r"(b[0]), "r"(b[1]));
}
// ---- fp16 pack ----
__device__ __forceinline__ uint32_t cvt2f16(float e, float o) {
    uint32_t r;
    asm("cvt.rn.f16x2.f32 %0, %1, %2;" : "=r"(r) : "f"(o), "f"(e));
    return r;
}
__device__ __forceinline__ float f16lo2f(uint32_t h) {
    float f;
    asm("{ .reg .f16 a, b; mov.b32 {a, b}, %1; cvt.f32.f16 %0, a; }"
        : "=f"(f) : "r"(h));
    return f;
}
__device__ __forceinline__ float f16hi2f(uint32_t h) {
    float f;
    asm("{ .reg .f16 a, b; mov.b32 {a, b}, %1; cvt.f32.f16 %0, b; }"
        : "=f"(f) : "r"(h));
    return f;
}
__device__ __forceinline__ void pack_pair_f16(float e, float o,
                                              uint32_t& hi, uint32_t& lo) {
    uint32_t h = cvt2f16(e, o);
    float re = e - f16lo2f(h);
    float ro = o - f16hi2f(h);
    hi = h;
    lo = cvt2f16(re, ro);
}
__device__ __forceinline__ float fast_ex2(float x) {
    float r;
    asm("ex2.approx.ftz.f32 %0, %1;" : "=f"(r) : "f"(x));
    return r;
}

// ===========================================================================
// Round kernel: fp32 -> fp16 (memory-bound)
// ===========================================================================
__global__ __launch_bounds__(256) void round_f16_kernel(
    const float* __restrict__ src, uint16_t* __restrict__ dst, int n4)
{
    int idx = blockIdx.x * blockDim.x + threadIdx.x;
    if (idx >= n4) return;
    float4 v = ((const float4*)src)[idx];
    ((uint2*)dst)[idx] = make_uint2(cvt2f16(v.x, v.y), cvt2f16(v.z, v.w));
}

// ===========================================================================
// FP16 GEMM (NT), TERMS-term A: C = (Ah[+Al]) Bh^T. 128x128 tile,
// K-chunks of 64, 8 warps 2Mx4N, 2-stage cp.async pipeline.
// SPLIT_OUT: Q,K cols -> 1-term fp16 qkv; V cols (n0>=2048) -> transposed
// fp16 VT [e][b*1024+l] via smem transpose.
// ===========================================================================
#define BSTR 72                         // smem row stride (elems) = 144 B
#define MTILE_B (128 * BSTR * 2)        // 18432 bytes per matrix tile
#define TSTR 136                         // transpose tile stride (elems)

template <int TERMS, bool SPLIT_OUT>
__global__ __launch_bounds__(256) void f16_gemm(
    const uint16_t* __restrict__ Ah, const uint16_t* __restrict__ Al,
    const uint16_t* __restrict__ Bh,
    const float* __restrict__ bias, float* __restrict__ C,
    uint16_t* __restrict__ outH,
    uint16_t* __restrict__ vtH,
    int M, int N, int K)
{
    extern __shared__ char smraw[];
    const uint32_t sb = smem_u32(smraw);
    const int tid  = threadIdx.x;
    const int wid  = tid >> 5, lane = tid & 31;
    const int m0   = blockIdx.y << 7, n0 = blockIdx.x << 7;
    const int wm   = (wid & 1) << 6;
    const int wn   = (wid >> 1) << 5;

    const uint32_t STG = (uint32_t)(TERMS + 1) * MTILE_B;
    uint32_t stg[2] = { sb, sb + STG };

    // loads: 128 rows x 8 16B-units per matrix -> 4 units per thread
    int lrw[4]; uint32_t so[4];
#pragma unroll
    for (int i = 0; i < 4; i++) {
        int idx = tid + (i << 8);
        int row = idx >> 3, c8 = idx & 7;
        lrw[i] = row;
        so[i] = (uint32_t)(row * BSTR + c8 * 8) * 2;
    }
    const int lco = (tid & 7) * 8;
    const uint16_t* gAh = Ah + (size_t)m0 * K + lco;
    const uint16_t* gAl = (TERMS == 2) ? (Al + (size_t)m0 * K + lco) : nullptr;
    const uint16_t* gBh = Bh + (size_t)n0 * K + lco;

    float acc[4][4][4];
#pragma unroll
    for (int i = 0; i < 4; i++)
#pragma unroll
        for (int j = 0; j < 4; j++)
#pragma unroll
            for (int k = 0; k < 4; k++) acc[i][j][k] = 0.f;

    const uint32_t arow = (uint32_t)(wm + (lane & 15));
    const uint32_t acol = (uint32_t)((lane >> 4) << 3);
    const uint32_t brow = (uint32_t)(wn + (lane & 7) + ((lane >> 4) & 1) * 8);
    const uint32_t bcol = (uint32_t)(((lane >> 3) & 1) << 3);

    const int NCH = K >> 6;             // 64-wide chunks

    // prologue: chunk 0 -> stage 0
    {
        uint32_t d = stg[0];
#pragma unroll
        for (int i = 0; i < 4; i++) {
            size_t g = (size_t)lrw[i] * K;
            cp_async16(d + 0 * MTILE_B + so[i], gAh + g);
            if (TERMS == 2)
                cp_async16(d + 1 * MTILE_B + so[i], gAl + g);
            cp_async16(d + TERMS * MTILE_B + so[i], gBh + g);
        }
    }
    CP_COMMIT();

    for (int ch = 0; ch < NCH; ch++) {
        const int s = ch & 1;
        CP_WAIT(0);
        __syncthreads();   // chunk ch visible; prior reads of stg[1-s] done
        if (ch + 1 < NCH) {
            const int k0 = (ch + 1) << 6;
            uint32_t d = stg[1 - s];
#pragma unroll
            for (int i = 0; i < 4; i++) {
                size_t g = (size_t)lrw[i] * K + k0;
                cp_async16(d + 0 * MTILE_B + so[i], gAh + g);
                if (TERMS == 2)
                    cp_async16(d + 1 * MTILE_B + so[i], gAl + g);
                cp_async16(d + TERMS * MTILE_B + so[i], gBh + g);
            }
            CP_COMMIT();
        }

        const uint32_t AHB = stg[s];
        const uint32_t ALB = stg[s] + MTILE_B;           // valid if TERMS==2
        const uint32_t BHB = stg[s] + TERMS * MTILE_B;

#pragma unroll
        for (int ks = 0; ks < 4; ks++) {
            const uint32_t kadd = (uint32_t)(ks * 32);   // 16 elems = 32 bytes
            uint32_t bh_[2][4];
#pragma unroll
            for (int j = 0; j < 2; j++)
                ldsm_x4(bh_[j], BHB + ((brow + j * 16) * BSTR + bcol) * 2 + kadd);
#pragma unroll
            for (int mip = 0; mip < 2; mip++) {
                const uint32_t off0 = ((arow + (2 * mip) * 16) * BSTR + acol) * 2 + kadd;
                const uint32_t off1 = ((arow + (2 * mip + 1) * 16) * BSTR + acol) * 2 + kadd;
                uint32_t ah0[4], ah1[4];
                ldsm_x4(ah0, AHB + off0);
                ldsm_x4(ah1, AHB + off1);
                if (TERMS == 2) {
                    uint32_t al0[4], al1[4];
                    ldsm_x4(al0, ALB + off0);
                    ldsm_x4(al1, ALB + off1);
#pragma unroll
                    for (int nj = 0; nj < 4; nj++)
                        mma_f16(acc[2 * mip][nj],     ah0, bh_[nj >> 1] + (nj & 1) * 2);
#pragma unroll
                    for (int nj = 0; nj < 4; nj++)
                        mma_f16(acc[2 * mip + 1][nj], ah1, bh_[nj >> 1] + (nj & 1) * 2);
#pragma unroll
                    for (int nj = 0; nj < 4; nj++)
                        mma_f16(acc[2 * mip][nj],     al0, bh_[nj >> 1] + (nj & 1) * 2);
#pragma unroll
                    for (int nj = 0; nj < 4; nj++)
                        mma_f16(acc[2 * mip + 1][nj], al1, bh_[nj >> 1] + (nj & 1) * 2);
                } else {
#pragma unroll
                    for (int nj = 0; nj < 4; nj++)
                        mma_f16(acc[2 * mip][nj],     ah0, bh_[nj >> 1] + (nj & 1) * 2);
#pragma unroll
                    for (int nj = 0; nj < 4; nj++)
                        mma_f16(acc[2 * mip + 1][nj], ah1, bh_[nj >> 1] + (nj & 1) * 2);
                }
            }
        }
    }

    const int rbase = m0 + wm + (lane >> 2);
    const int cbase = n0 + wn + ((lane & 3) << 1);

    if (SPLIT_OUT && n0 >= 2 * INNER) {
        // ---- V columns: transpose via smem (1 pass), store fp16 VT ----
        uint16_t* T = (uint16_t*)smraw;
        const int b  = m0 >> 10;
        const int l0 = m0 & 1023;
        __syncthreads();   // mainloop reads done
        const int rloc = wm + (lane >> 2);
        const int cloc = wn + ((lane & 3) << 1);
#pragma unroll
        for (int nj = 0; nj < 4; nj++) {
#pragma unroll
            for (int mi = 0; mi < 4; mi++) {
                uint32_t w0 = cvt2f16(acc[mi][nj][0], acc[mi][nj][1]);
                uint32_t w1 = cvt2f16(acc[mi][nj][2], acc[mi][nj][3]);
                int c = cloc + nj * 8;
                int r = rloc + mi * 16;
                T[c * TSTR + r]           = (uint16_t)(w0 & 0xffffu);
                T[(c + 1) * TSTR + r]     = (uint16_t)(w0 >> 16);
                T[c * TSTR + r + 8]       = (uint16_t)(w1 & 0xffffu);
                T[(c + 1) * TSTR + r + 8] = (uint16_t)(w1 >> 16);
            }
        }
        __syncthreads();
        // Drain FULL tile: 128 cols x 16 8-row units.
#pragma unroll
        for (int i = 0; i < 8; i++) {
            int idx = tid + (i << 8);
            int c = idx >> 4, u = idx & 15;
            int e = n0 - 2 * INNER + c;
            size_t dst = ((size_t)e * BB + b) * LL + l0 + u * 8;
            *(uint4*)(vtH + dst) = *(const uint4*)(T + c * TSTR + u * 8);
        }
    } else {
#pragma unroll
        for (int nj = 0; nj < 4; nj++) {
            const int col = cbase + nj * 8;
            if (SPLIT_OUT) {
#pragma unroll
                for (int mi = 0; mi < 4; mi++) {
                    const int r0 = rbase + mi * 16;
                    uint32_t h0 = cvt2f16(acc[mi][nj][0], acc[mi][nj][1]);
                    uint32_t h1 = cvt2f16(acc[mi][nj][2], acc[mi][nj][3]);
                    *(uint32_t*)(outH + (size_t)r0 * N + col) = h0;
                    *(uint32_t*)(outH + (size_t)(r0 + 8) * N + col) = h1;
                }
            } else {
                float b0 = bias[col], b1 = bias[col + 1];
#pragma unroll
                for (int mi = 0; mi < 4; mi++) {
                    const int r0 = rbase + mi * 16;
                    float2 v0 = { acc[mi][nj][0] + b0, acc[mi][nj][1] + b1 };
                    float2 v1 = { acc[mi][nj][2] + b0, acc[mi][nj][3] + b1 };
                    *(float2*)(C + (size_t)r0 * N + col) = v0;
                    *(float2*)(C + (size_t)(r0 + 8) * N + col) = v1;
                }
            }
        }
    }
}

// ===========================================================================
// Tensor-core attention, 1-term fp16 operands (round-13/14 proven, unchanged).
// ===========================================================================
#define AT_STR 72
#define AQ 0
#define AK (128 * AT_STR)
#define AV (192 * AT_STR)
#define AT_ELEMS (256 * AT_STR)
#define AT_SMEM_BYTES (AT_ELEMS * 2)    // 36864 bytes

__global__ __launch_bounds__(256) void attn_kernel(
    const uint16_t* __restrict__ qh,
    const uint16_t* __restrict__ vth,
    uint16_t* __restrict__ oh, uint16_t* __restrict__ ol)
{
    extern __shared__ uint16_t sm16[];
    const uint32_t sb = smem_u32(sm16);
    const int tid = threadIdx.x, wid = tid >> 5, lane = tid & 31;
    const int bh = blockIdx.x, b = bh >> 4, h = bh & 15;
    const int q0 = blockIdx.y << 7;
    const size_t rowbase = (size_t)b * LL;

    // ---- Q tile: 128 rows x 64 cols fp16 ----
#pragma unroll
    for (int i = 0; i < 4; i++) {
        int idx = tid + (i << 8);
        if (idx < 1024) {
            int r = idx >> 3, c8 = idx & 7;
            size_t g = (rowbase + q0 + r) * QKV_N + h * 64 + c8 * 8;
            *(uint4*)(sm16 + AQ + r * AT_STR + c8 * 8) = *(const uint4*)(qh + g);
        }
    }
    __syncthreads();

    uint32_t qf[4][4];
    {
        const uint32_t qrow = (uint32_t)((wid << 4) + (lane & 15));
        const uint32_t cc = (uint32_t)((lane >> 4) << 3);
#pragma unroll
        for (int ks = 0; ks < 4; ks++) {
            uint32_t off = (uint32_t)(qrow * AT_STR + ks * 16 + cc) * 2;
            ldsm_x4(qf[ks], sb + AQ * 2 + off);
        }
    }

    float oacc[8][4];
#pragma unroll
    for (int i = 0; i < 8; i++)
#pragma unroll
        for (int j = 0; j < 4; j++) oacc[i][j] = 0.f;
    float ls0 = 0.f, ls1 = 0.f;

    const float CE = 0.125f * 1.4426950408889634f;
    const uint32_t KB = sb + AK * 2, VBa = sb + AV * 2;

    for (int kt = 0; kt < 16; kt++) {
        __syncthreads();

#pragma unroll
        for (int i = 0; i < 2; i++) {
            int idx = tid + (i << 8);
            int r = idx >> 3, c8 = idx & 7;
            size_t gk = (rowbase + kt * 64 + r) * QKV_N + INNER
                        + h * 64 + c8 * 8;
            size_t gv = ((size_t)(h * 64 + r) * BB + b) * LL + kt * 64 + c8 * 8;
            *(uint4*)(sm16 + AK + r * AT_STR + c8 * 8) = *(const uint4*)(qh + gk);
            *(uint4*)(sm16 + AV + r * AT_STR + c8 * 8) = *(const uint4*)(vth + gv);
        }
        __syncthreads();

        // ---- S = Q K^T (1-term fp16) ----
        float p[8][4];
#pragma unroll
        for (int i = 0; i < 8; i++)
#pragma unroll
            for (int j = 0; j < 4; j++) p[i][j] = 0.f;

#pragma unroll
        for (int ks = 0; ks < 4; ks++) {
#pragma unroll
            for (int njp = 0; njp < 4; njp++) {
                uint32_t kf[4];
                uint32_t roff = (uint32_t)(njp * 16 + (lane & 7)
                                           + ((lane >> 4) & 1) * 8);
                uint32_t coff = (uint32_t)(ks * 16 + ((lane >> 3) & 1) * 8);
                ldsm_x4(kf, KB + (roff * AT_STR + coff) * 2);
                mma_f16(p[2 * njp],     qf[ks], kf);
                mma_f16(p[2 * njp + 1], qf[ks], kf + 2);
            }
        }

        // ---- exp (clamped, exponent shifted -8 for fp16 range) ----
#pragma unroll
        for (int nt = 0; nt < 8; nt++) {
#pragma unroll
            for (int q = 0; q < 4; q++) {
                float a_ = fminf(p[nt][q] * CE, 80.f) - 8.f;
                p[nt][q] = fast_ex2(a_);
            }
            ls0 += p[nt][0] + p[nt][1];
            ls1 += p[nt][2] + p[nt][3];
        }

        // ---- repack P -> fp16 A-frags ----
        uint32_t pa[4][4];
#pragma unroll
        for (int ks = 0; ks < 4; ks++) {
            pa[ks][0] = cvt2f16(p[2 * ks][0],     p[2 * ks][1]);
            pa[ks][1] = cvt2f16(p[2 * ks][2],     p[2 * ks][3]);
            pa[ks][2] = cvt2f16(p[2 * ks + 1][0], p[2 * ks + 1][1]);
            pa[ks][3] = cvt2f16(p[2 * ks + 1][2], p[2 * ks + 1][3]);
        }

        // ---- O += P V (1-term fp16) ----
#pragma unroll
        for (int ks = 0; ks < 4; ks++) {
#pragma unroll
            for (int dtp = 0; dtp < 4; dtp++) {
                uint32_t vf[4];
                uint32_t roff = (uint32_t)(dtp * 16 + (lane & 7)
                                           + ((lane >> 4) & 1) * 8);
                uint32_t coff = (uint32_t)(ks * 16 + ((lane >> 3) & 1) * 8);
                ldsm_x4(vf, VBa + (roff * AT_STR + coff) * 2);
                mma_f16(oacc[2 * dtp],     pa[ks], vf);
                mma_f16(oacc[2 * dtp + 1], pa[ks], vf + 2);
            }
        }
    }

    // ---- epilogue: normalize + fp16 2-term split-store ----
    ls0 += __shfl_xor_sync(0xffffffffu, ls0, 1);
    ls0 += __shfl_xor_sync(0xffffffffu, ls0, 2);
    ls1 += __shfl_xor_sync(0xffffffffu, ls1, 1);
    ls1 += __shfl_xor_sync(0xffffffffu, ls1, 2);
    const float i0 = 1.f / fmaxf(ls0, 1e-30f);
    const float i1 = 1.f / fmaxf(ls1, 1e-30f);

    const int r0 = q0 + (wid << 4) + (lane >> 2);
    const int col = h * 64 + ((lane & 3) << 1);
#pragma unroll
    for (int dt = 0; dt < 8; dt++) {
        uint32_t h0, l0, h1, l1;
        pack_pair_f16(oacc[dt][0] * i0, oacc[dt][1] * i0, h0, l0);
        pack_pair_f16(oacc[dt][2] * i1, oacc[dt][3] * i1, h1, l1);
        size_t g0 = (rowbase + r0) * INNER + col + dt * 8;
        size_t g1 = (rowbase + r0 + 8) * INNER + col + dt * 8;
        *(uint32_t*)(oh + g0) = h0;
        *(uint32_t*)(ol + g0) = l0;
        *(uint32_t*)(oh + g1) = h1;
        *(uint32_t*)(ol + g1) = l1;
    }
}

// ---------------------------------------------------------------------------
// In-place LayerNorm (biased variance), one 256-thread block per row.
// ---------------------------------------------------------------------------
__global__ __launch_bounds__(256) void ln_kernel(
    float* __restrict__ Y, const float* __restrict__ gamma,
    const float* __restrict__ beta)
{
    const int row = blockIdx.x;
    float* y = Y + (size_t)row * DD;
    const int tid = threadIdx.x;

    float v[4];
    float s = 0.f, ss = 0.f;
#pragma unroll
    for (int i = 0; i < 4; i++) {
        v[i] = y[tid + (i << 8)];
        s += v[i];
        ss += v[i] * v[i];
    }
#pragma unroll
    for (int o = 16; o; o >>= 1) {
        s  += __shfl_xor_sync(0xffffffffu, s, o);
        ss += __shfl_xor_sync(0xffffffffu, ss, o);
    }
    __shared__ float rs[8], rss[8], mv[2];
    int w = tid >> 5, lane = tid & 31;
    if (!lane) { rs[w] = s; rss[w] = ss; }
    __syncthreads();
    if (tid == 0) {
        float S = 0.f, SS = 0.f;
#pragma unroll
        for (int i = 0; i < 8; i++) { S += rs[i]; SS += rss[i]; }
        float mean = S * (1.f / 1024.f);
        float var  = SS * (1.f / 1024.f) - mean * mean;
        mv[0] = mean;
        mv[1] = rsqrtf(var + 1e-5f);
    }
    __syncthreads();
    float mean = mv[0], rstd = mv[1];
#pragma unroll
    for (int i = 0; i < 4; i++) {
        int d = tid + (i << 8);
        y[d] = (v[i] - mean) * rstd * gamma[d] + beta[d];
    }
}

// ---------------------------------------------------------------------------
// Launch
// ---------------------------------------------------------------------------
extern "C" void kernel_launch(void* const* d_in, const int* in_sizes, int n_in,
                              void* d_out, int out_size)
{
    const float* x     = (const float*)d_in[0];
    const float* w_qkv = (const float*)d_in[2];
    const float* w_out = (const float*)d_in[3];
    const float* b_out = (const float*)d_in[4];
    const float* gamma = (const float*)d_in[5];
    const float* beta  = (const float*)d_in[6];
    float* out = (float*)d_out;

    uint16_t *xh, *wqh, *woh, *qh, *vth, *ah, *al;
    cudaGetSymbolAddress((void**)&xh,  g_xh);
    cudaGetSymbolAddress((void**)&wqh, g_wqh);
    cudaGetSymbolAddress((void**)&woh, g_woh);
    cudaGetSymbolAddress((void**)&qh,  g_qh);
    cudaGetSymbolAddress((void**)&vth, g_vth);
    cudaGetSymbolAddress((void**)&ah,  g_ah);
    cudaGetSymbolAddress((void**)&al,  g_al);

    const int SMEM_T1 = 4 * MTILE_B;   // 73728
    const int SMEM_T2 = 6 * MTILE_B;   // 110592
    cudaFuncSetAttribute(f16_gemm<1, true>,
                         cudaFuncAttributeMaxDynamicSharedMemorySize, SMEM_T1);
    cudaFuncSetAttribute(f16_gemm<2, false>,
                         cudaFuncAttributeMaxDynamicSharedMemorySize, SMEM_T2);
    cudaFuncSetAttribute(attn_kernel,
                         cudaFuncAttributeMaxDynamicSharedMemorySize,
                         AT_SMEM_BYTES);

    // 0) Round x and weights to fp16 (1-term)
    round_f16_kernel<<<(M1 * DD / 4 + 255) / 256, 256>>>(x, xh, M1 * DD / 4);
    round_f16_kernel<<<(QKV_N * DD / 4 + 255) / 256, 256>>>(w_qkv, wqh,
                                                            QKV_N * DD / 4);
    round_f16_kernel<<<(DD * INNER / 4 + 255) / 256, 256>>>(w_out, woh,
                                                            DD * INNER / 4);

    // 1) QKV projection (1-term A): Q,K -> fp16 qkv; V -> transposed fp16 VT
    f16_gemm<1, true><<<dim3(QKV_N / 128, M1 / 128), 256, SMEM_T1>>>(
        xh, nullptr, wqh, nullptr, nullptr, qh, vth, M1, QKV_N, DD);

    // 2) Attention (1-term fp16 MMA) -> fp16 2-term split output
    attn_kernel<<<dim3(BB * HH, LL / 128), 256, AT_SMEM_BYTES>>>(
        qh, vth, ah, al);

    // 3) Output projection (2-term A) + bias -> d_out
    f16_gemm<2, false><<<dim3(INNER / 128, M1 / 128), 256, SMEM_T2>>>(
        ah, al, woh, b_out, out, nullptr, nullptr, M1, DD, INNER);

    // 4) LayerNorm in-place
    ln_kernel<<<M1, 256>>>(out, gamma, beta);
}

// round 16
// speedup vs baseline: 1.8856x; 1.0472x over previous
#include <cuda_runtime.h>
#include <cstdint>
#include <cstddef>

// Problem constants
#define BB 4
#define LL 1024
#define DD 1024
#define HH 16
#define INNER 1024          // H*HD
#define M1 4096             // B*L
#define QKV_N 3072          // 3*INNER

// Scratch (static device allocations — allowed)
__device__ uint16_t g_xh[(size_t)M1 * DD];      // x fp16 (1-term)
__device__ uint16_t g_wqh[(size_t)QKV_N * DD];  // w_qkv fp16 (1-term)
__device__ uint16_t g_woh[(size_t)DD * INNER];  // w_out fp16 (1-term)
__device__ uint16_t g_qh[(size_t)M1 * QKV_N];   // qkv fp16 (Q,K used)
__device__ uint16_t g_vth[(size_t)HH * 64 * BB * LL];  // V^T fp16 [e][b][l]
__device__ uint16_t g_ah[(size_t)M1 * INNER];   // attention out (fp16 hi)
__device__ uint16_t g_al[(size_t)M1 * INNER];   // attention out (fp16 lo)

// ===========================================================================
// Portable PTX helpers
// ===========================================================================
__device__ __forceinline__ uint32_t smem_u32(const void* p) {
    uint32_t a;
    asm("{ .reg .u64 t; cvta.to.shared.u64 t, %1; cvt.u32.u64 %0, t; }"
        : "=r"(a) : "l"(p));
    return a;
}
__device__ __forceinline__ void cp_async16(uint32_t dst, const void* src) {
    asm volatile("cp.async.cg.shared.global [%0], [%1], 16;"
                 :: "r"(dst), "l"(src) : "memory");
}
#define CP_COMMIT() asm volatile("cp.async.commit_group;" ::: "memory")
#define CP_WAIT(n)  asm volatile("cp.async.wait_group %0;" :: "n"(n) : "memory")

__device__ __forceinline__ void ldsm_x4(uint32_t* r, uint32_t addr) {
    asm volatile("ldmatrix.sync.aligned.m8n8.x4.shared.b16 {%0,%1,%2,%3}, [%4];"
                 : "=r"(r[0]), "=r"(r[1]), "=r"(r[2]), "=r"(r[3]) : "r"(addr));
}
__device__ __forceinline__ void mma_f16(float* d, const uint32_t* a,
                                        const uint32_t* b) {
    asm volatile(
        "mma.sync.aligned.m16n8k16.row.col.f32.f16.f16.f32 "
        "{%0,%1,%2,%3}, {%4,%5,%6,%7}, {%8,%9}, {%0,%1,%2,%3};"
        : "+f"(d[0]), "+f"(d[1]), "+f"(d[2]), "+f"(d[3])
        : "r"(a[0]), "r"(a[1]), "r"(a[2]), "r"(a[3]), "r"(b[0]), "r"(b[1]));
}
// ---- fp16 pack ----
__device__ __forceinline__ uint32_t cvt2f16(float e, float o) {
    uint32_t r;
    asm("cvt.rn.f16x2.f32 %0, %1, %2;" : "=r"(r) : "f"(o), "f"(e));
    return r;
}
__device__ __forceinline__ float f16lo2f(uint32_t h) {
    float f;
    asm("{ .reg .f16 a, b; mov.b32 {a, b}, %1; cvt.f32.f16 %0, a; }"
        : "=f"(f) : "r"(h));
    return f;
}
__device__ __forceinline__ float f16hi2f(uint32_t h) {
    float f;
    asm("{ .reg .f16 a, b; mov.b32 {a, b}, %1; cvt.f32.f16 %0, b; }"
        : "=f"(f) : "r"(h));
    return f;
}
__device__ __forceinline__ void pack_pair_f16(float e, float o,
                                              uint32_t& hi, uint32_t& lo) {
    uint32_t h = cvt2f16(e, o);
    float re = e - f16lo2f(h);
    float ro = o - f16hi2f(h);
    hi = h;
    lo = cvt2f16(re, ro);
}
__device__ __forceinline__ float fast_ex2(float x) {
    float r;
    asm("ex2.approx.ftz.f32 %0, %1;" : "=f"(r) : "f"(x));
    return r;
}

// ===========================================================================
// Round kernel: fp32 -> fp16 (memory-bound)
// ===========================================================================
__global__ __launch_bounds__(256) void round_f16_kernel(
    const float* __restrict__ src, uint16_t* __restrict__ dst, int n4)
{
    int idx = blockIdx.x * blockDim.x + threadIdx.x;
    if (idx >= n4) return;
    float4 v = ((const float4*)src)[idx];
    ((uint2*)dst)[idx] = make_uint2(cvt2f16(v.x, v.y), cvt2f16(v.z, v.w));
}

// ===========================================================================
// FP16 GEMM (NT), TERMS-term A: C = (Ah[+Al]) Bh^T. 128x128 tile,
// K-chunks of 64, 8 warps 2Mx4N, 2-stage cp.async pipeline.
// TERMS==1 mainloop: A-ldsm hoisted per ks, B-frags double-buffered across
// ks (next-ks B in flight under current-ks MMAs).
// SPLIT_OUT: Q,K cols -> 1-term fp16 qkv; V cols (n0>=2048) -> transposed
// fp16 VT [e][b*1024+l] via smem transpose.
// ===========================================================================
#define BSTR 72                         // smem row stride (elems) = 144 B
#define MTILE_B (128 * BSTR * 2)        // 18432 bytes per matrix tile
#define TSTR 136                         // transpose tile stride (elems)

template <int TERMS, bool SPLIT_OUT>
__global__ __launch_bounds__(256) void f16_gemm(
    const uint16_t* __restrict__ Ah, const uint16_t* __restrict__ Al,
    const uint16_t* __restrict__ Bh,
    const float* __restrict__ bias, float* __restrict__ C,
    uint16_t* __restrict__ outH,
    uint16_t* __restrict__ vtH,
    int M, int N, int K)
{
    extern __shared__ char smraw[];
    const uint32_t sb = smem_u32(smraw);
    const int tid  = threadIdx.x;
    const int wid  = tid >> 5, lane = tid & 31;
    const int m0   = blockIdx.y << 7, n0 = blockIdx.x << 7;
    const int wm   = (wid & 1) << 6;
    const int wn   = (wid >> 1) << 5;

    const uint32_t STG = (uint32_t)(TERMS + 1) * MTILE_B;
    uint32_t stg[2] = { sb, sb + STG };

    // loads: 128 rows x 8 16B-units per matrix -> 4 units per thread
    int lrw[4]; uint32_t so[4];
#pragma unroll
    for (int i = 0; i < 4; i++) {
        int idx = tid + (i << 8);
        int row = idx >> 3, c8 = idx & 7;
        lrw[i] = row;
        so[i] = (uint32_t)(row * BSTR + c8 * 8) * 2;
    }
    const int lco = (tid & 7) * 8;
    const uint16_t* gAh = Ah + (size_t)m0 * K + lco;
    const uint16_t* gAl = (TERMS == 2) ? (Al + (size_t)m0 * K + lco) : nullptr;
    const uint16_t* gBh = Bh + (size_t)n0 * K + lco;

    float acc[4][4][4];
#pragma unroll
    for (int i = 0; i < 4; i++)
#pragma unroll
        for (int j = 0; j < 4; j++)
#pragma unroll
            for (int k = 0; k < 4; k++) acc[i][j][k] = 0.f;

    const uint32_t arow = (uint32_t)(wm + (lane & 15));
    const uint32_t acol = (uint32_t)((lane >> 4) << 3);
    const uint32_t brow = (uint32_t)(wn + (lane & 7) + ((lane >> 4) & 1) * 8);
    const uint32_t bcol = (uint32_t)(((lane >> 3) & 1) << 3);

    const int NCH = K >> 6;             // 64-wide chunks

    // prologue: chunk 0 -> stage 0
    {
        uint32_t d = stg[0];
#pragma unroll
        for (int i = 0; i < 4; i++) {
            size_t g = (size_t)lrw[i] * K;
            cp_async16(d + 0 * MTILE_B + so[i], gAh + g);
            if (TERMS == 2)
                cp_async16(d + 1 * MTILE_B + so[i], gAl + g);
            cp_async16(d + TERMS * MTILE_B + so[i], gBh + g);
        }
    }
    CP_COMMIT();

    for (int ch = 0; ch < NCH; ch++) {
        const int s = ch & 1;
        CP_WAIT(0);
        __syncthreads();   // chunk ch visible; prior reads of stg[1-s] done
        if (ch + 1 < NCH) {
            const int k0 = (ch + 1) << 6;
            uint32_t d = stg[1 - s];
#pragma unroll
            for (int i = 0; i < 4; i++) {
                size_t g = (size_t)lrw[i] * K + k0;
                cp_async16(d + 0 * MTILE_B + so[i], gAh + g);
                if (TERMS == 2)
                    cp_async16(d + 1 * MTILE_B + so[i], gAl + g);
                cp_async16(d + TERMS * MTILE_B + so[i], gBh + g);
            }
            CP_COMMIT();
        }

        const uint32_t AHB = stg[s];
        const uint32_t ALB = stg[s] + MTILE_B;           // valid if TERMS==2
        const uint32_t BHB = stg[s] + TERMS * MTILE_B;

        if (TERMS == 1) {
            // B-frag double buffer across ks; A-ldsm hoisted per ks.
            uint32_t bf[2][8];
            ldsm_x4(&bf[0][0], BHB + (brow * BSTR + bcol) * 2);
            ldsm_x4(&bf[0][4], BHB + ((brow + 16) * BSTR + bcol) * 2);
#pragma unroll
            for (int ks = 0; ks < 4; ks++) {
                const int cur = ks & 1;
                const uint32_t kadd = (uint32_t)(ks * 32);
                uint32_t af[4][4];
#pragma unroll
                for (int mi = 0; mi < 4; mi++)
                    ldsm_x4(af[mi],
                            AHB + ((arow + mi * 16) * BSTR + acol) * 2 + kadd);
                if (ks < 3) {
                    const uint32_t kn = kadd + 32;
                    ldsm_x4(&bf[1 - cur][0], BHB + (brow * BSTR + bcol) * 2 + kn);
                    ldsm_x4(&bf[1 - cur][4],
                            BHB + ((brow + 16) * BSTR + bcol) * 2 + kn);
                }
#pragma unroll
                for (int mi = 0; mi < 4; mi++)
#pragma unroll
                    for (int nj = 0; nj < 4; nj++)
                        mma_f16(acc[mi][nj], af[mi],
                                &bf[cur][(nj >> 1) * 4 + (nj & 1) * 2]);
            }
        } else {
#pragma unroll
            for (int ks = 0; ks < 4; ks++) {
                const uint32_t kadd = (uint32_t)(ks * 32);
                uint32_t bh_[2][4];
#pragma unroll
                for (int j = 0; j < 2; j++)
                    ldsm_x4(bh_[j],
                            BHB + ((brow + j * 16) * BSTR + bcol) * 2 + kadd);
#pragma unroll
                for (int mip = 0; mip < 2; mip++) {
                    const uint32_t off0 =
                        ((arow + (2 * mip) * 16) * BSTR + acol) * 2 + kadd;
                    const uint32_t off1 =
                        ((arow + (2 * mip + 1) * 16) * BSTR + acol) * 2 + kadd;
                    uint32_t ah0[4], ah1[4], al0[4], al1[4];
                    ldsm_x4(ah0, AHB + off0);
                    ldsm_x4(ah1, AHB + off1);
                    ldsm_x4(al0, ALB + off0);
                    ldsm_x4(al1, ALB + off1);
#pragma unroll
                    for (int nj = 0; nj < 4; nj++)
                        mma_f16(acc[2 * mip][nj],     ah0, bh_[nj >> 1] + (nj & 1) * 2);
#pragma unroll
                    for (int nj = 0; nj < 4; nj++)
                        mma_f16(acc[2 * mip + 1][nj], ah1, bh_[nj >> 1] + (nj & 1) * 2);
#pragma unroll
                    for (int nj = 0; nj < 4; nj++)
                        mma_f16(acc[2 * mip][nj],     al0, bh_[nj >> 1] + (nj & 1) * 2);
#pragma unroll
                    for (int nj = 0; nj < 4; nj++)
                        mma_f16(acc[2 * mip + 1][nj], al1, bh_[nj >> 1] + (nj & 1) * 2);
                }
            }
        }
    }

    const int rbase = m0 + wm + (lane >> 2);
    const int cbase = n0 + wn + ((lane & 3) << 1);

    if (SPLIT_OUT && n0 >= 2 * INNER) {
        // ---- V columns: transpose via smem (1 pass), store fp16 VT ----
        uint16_t* T = (uint16_t*)smraw;
        const int b  = m0 >> 10;
        const int l0 = m0 & 1023;
        __syncthreads();   // mainloop reads done
        const int rloc = wm + (lane >> 2);
        const int cloc = wn + ((lane & 3) << 1);
#pragma unroll
        for (int nj = 0; nj < 4; nj++) {
#pragma unroll
            for (int mi = 0; mi < 4; mi++) {
                uint32_t w0 = cvt2f16(acc[mi][nj][0], acc[mi][nj][1]);
                uint32_t w1 = cvt2f16(acc[mi][nj][2], acc[mi][nj][3]);
                int c = cloc + nj * 8;
                int r = rloc + mi * 16;
                T[c * TSTR + r]           = (uint16_t)(w0 & 0xffffu);
                T[(c + 1) * TSTR + r]     = (uint16_t)(w0 >> 16);
                T[c * TSTR + r + 8]       = (uint16_t)(w1 & 0xffffu);
                T[(c + 1) * TSTR + r + 8] = (uint16_t)(w1 >> 16);
            }
        }
        __syncthreads();
        // Drain FULL tile: 128 cols x 16 8-row units.
#pragma unroll
        for (int i = 0; i < 8; i++) {
            int idx = tid + (i << 8);
            int c = idx >> 4, u = idx & 15;
            int e = n0 - 2 * INNER + c;
            size_t dst = ((size_t)e * BB + b) * LL + l0 + u * 8;
            *(uint4*)(vtH + dst) = *(const uint4*)(T + c * TSTR + u * 8);
        }
    } else {
#pragma unroll
        for (int nj = 0; nj < 4; nj++) {
            const int col = cbase + nj * 8;
            if (SPLIT_OUT) {
#pragma unroll
                for (int mi = 0; mi < 4; mi++) {
                    const int r0 = rbase + mi * 16;
                    uint32_t h0 = cvt2f16(acc[mi][nj][0], acc[mi][nj][1]);
                    uint32_t h1 = cvt2f16(acc[mi][nj][2], acc[mi][nj][3]);
                    *(uint32_t*)(outH + (size_t)r0 * N + col) = h0;
                    *(uint32_t*)(outH + (size_t)(r0 + 8) * N + col) = h1;
                }
            } else {
                float b0 = bias[col], b1 = bias[col + 1];
#pragma unroll
                for (int mi = 0; mi < 4; mi++) {
                    const int r0 = rbase + mi * 16;
                    float2 v0 = { acc[mi][nj][0] + b0, acc[mi][nj][1] + b1 };
                    float2 v1 = { acc[mi][nj][2] + b0, acc[mi][nj][3] + b1 };
                    *(float2*)(C + (size_t)r0 * N + col) = v0;
                    *(float2*)(C + (size_t)(r0 + 8) * N + col) = v1;
                }
            }
        }
    }
}

// ===========================================================================
// Tensor-core attention, 1-term fp16 operands (round-13/14/15 arithmetic,
// unchanged). KV tiles double-buffered via cp.async using the proven GEMM
// skeleton (wait(0) -> sync -> prefetch -> compute). Smem 55 KB: occupancy
// unchanged (reg-limited 2 CTAs/SM).
// ===========================================================================
#define AT_STR 72
#define AQ 0
#define AKV (128 * AT_STR)              // stage 0 base (elems)
#define ASTG (128 * AT_STR)             // stage stride: K 64 rows + V 64 rows
#define AT_ELEMS (AKV + 2 * ASTG)
#define AT_SMEM_BYTES (AT_ELEMS * 2)    // 55296 bytes

__global__ __launch_bounds__(256) void attn_kernel(
    const uint16_t* __restrict__ qh,
    const uint16_t* __restrict__ vth,
    uint16_t* __restrict__ oh, uint16_t* __restrict__ ol)
{
    extern __shared__ uint16_t sm16[];
    const uint32_t sb = smem_u32(sm16);
    const int tid = threadIdx.x, wid = tid >> 5, lane = tid & 31;
    const int bh = blockIdx.x, b = bh >> 4, h = bh & 15;
    const int q0 = blockIdx.y << 7;
    const size_t rowbase = (size_t)b * LL;

    // ---- Q tile: 128 rows x 64 cols fp16 (plain loads, once) ----
#pragma unroll
    for (int i = 0; i < 4; i++) {
        int idx = tid + (i << 8);
        if (idx < 1024) {
            int r = idx >> 3, c8 = idx & 7;
            size_t g = (rowbase + q0 + r) * QKV_N + h * 64 + c8 * 8;
            *(uint4*)(sm16 + AQ + r * AT_STR + c8 * 8) = *(const uint4*)(qh + g);
        }
    }

    // ---- per-thread KV cp.async slots ----
    const int lr = tid >> 3, lc8 = tid & 7;     // lr 0..31 (+32), lc8 0..7
    const uint32_t KV0 = sb + (uint32_t)AKV * 2;
    const uint32_t STGB = (uint32_t)ASTG * 2;
    const uint32_t VOFF = (uint32_t)(64 * AT_STR) * 2;   // V base in stage

    // prologue: KV tile 0 -> stage 0
    {
        uint32_t d = KV0;
#pragma unroll
        for (int i = 0; i < 2; i++) {
            int r = lr + i * 32;
            uint32_t dl = (uint32_t)(r * AT_STR + lc8 * 8) * 2;
            size_t gk = (rowbase + r) * QKV_N + INNER + h * 64 + lc8 * 8;
            size_t gv = ((size_t)(h * 64 + r) * BB + b) * LL + lc8 * 8;
            cp_async16(d + dl, qh + gk);
            cp_async16(d + VOFF + dl, vth + gv);
        }
    }
    CP_COMMIT();
    __syncthreads();   // Q tile visible for ldsm

    uint32_t qf[4][4];
    {
        const uint32_t qrow = (uint32_t)((wid << 4) + (lane & 15));
        const uint32_t cc = (uint32_t)((lane >> 4) << 3);
#pragma unroll
        for (int ks = 0; ks < 4; ks++) {
            uint32_t off = (uint32_t)(qrow * AT_STR + ks * 16 + cc) * 2;
            ldsm_x4(qf[ks], sb + AQ * 2 + off);
        }
    }

    float oacc[8][4];
#pragma unroll
    for (int i = 0; i < 8; i++)
#pragma unroll
        for (int j = 0; j < 4; j++) oacc[i][j] = 0.f;
    float ls0 = 0.f, ls1 = 0.f;

    const float CE = 0.125f * 1.4426950408889634f;

    for (int kt = 0; kt < 16; kt++) {
        CP_WAIT(0);
        __syncthreads();   // KV(kt) visible; reads of other stage done

        if (kt + 1 < 16) {
            uint32_t d = KV0 + ((kt + 1) & 1) * STGB;
#pragma unroll
            for (int i = 0; i < 2; i++) {
                int r = lr + i * 32;
                uint32_t dl = (uint32_t)(r * AT_STR + lc8 * 8) * 2;
                size_t gk = (rowbase + (kt + 1) * 64 + r) * QKV_N + INNER
                            + h * 64 + lc8 * 8;
                size_t gv = ((size_t)(h * 64 + r) * BB + b) * LL
                            + (kt + 1) * 64 + lc8 * 8;
                cp_async16(d + dl, qh + gk);
                cp_async16(d + VOFF + dl, vth + gv);
            }
            CP_COMMIT();
        }

        const uint32_t base = KV0 + (kt & 1) * STGB;
        const uint32_t KB = base, VBa = base + VOFF;

        // ---- S = Q K^T (1-term fp16) ----
        float p[8][4];
#pragma unroll
        for (int i = 0; i < 8; i++)
#pragma unroll
            for (int j = 0; j < 4; j++) p[i][j] = 0.f;

#pragma unroll
        for (int ks = 0; ks < 4; ks++) {
#pragma unroll
            for (int njp = 0; njp < 4; njp++) {
                uint32_t kf[4];
                uint32_t roff = (uint32_t)(njp * 16 + (lane & 7)
                                           + ((lane >> 4) & 1) * 8);
                uint32_t coff = (uint32_t)(ks * 16 + ((lane >> 3) & 1) * 8);
                ldsm_x4(kf, KB + (roff * AT_STR + coff) * 2);
                mma_f16(p[2 * njp],     qf[ks], kf);
                mma_f16(p[2 * njp + 1], qf[ks], kf + 2);
            }
        }

        // ---- exp (clamped, exponent shifted -8 for fp16 range) ----
#pragma unroll
        for (int nt = 0; nt < 8; nt++) {
#pragma unroll
            for (int q = 0; q < 4; q++) {
                float a_ = fminf(p[nt][q] * CE, 80.f) - 8.f;
                p[nt][q] = fast_ex2(a_);
            }
            ls0 += p[nt][0] + p[nt][1];
            ls1 += p[nt][2] + p[nt][3];
        }

        // ---- repack P -> fp16 A-frags ----
        uint32_t pa[4][4];
#pragma unroll
        for (int ks = 0; ks < 4; ks++) {
            pa[ks][0] = cvt2f16(p[2 * ks][0],     p[2 * ks][1]);
            pa[ks][1] = cvt2f16(p[2 * ks][2],     p[2 * ks][3]);
            pa[ks][2] = cvt2f16(p[2 * ks + 1][0], p[2 * ks + 1][1]);
            pa[ks][3] = cvt2f16(p[2 * ks + 1][2], p[2 * ks + 1][3]);
        }

        // ---- O += P V (1-term fp16) ----
#pragma unroll
        for (int ks = 0; ks < 4; ks++) {
#pragma unroll
            for (int dtp = 0; dtp < 4; dtp++) {
                uint32_t vf[4];
                uint32_t roff = (uint32_t)(dtp * 16 + (lane & 7)
                                           + ((lane >> 4) & 1) * 8);
                uint32_t coff = (uint32_t)(ks * 16 + ((lane >> 3) & 1) * 8);
                ldsm_x4(vf, VBa + (roff * AT_STR + coff) * 2);
                mma_f16(oacc[2 * dtp],     pa[ks], vf);
                mma_f16(oacc[2 * dtp + 1], pa[ks], vf + 2);
            }
        }
    }

    // ---- epilogue: normalize + fp16 2-term split-store ----
    ls0 += __shfl_xor_sync(0xffffffffu, ls0, 1);
    ls0 += __shfl_xor_sync(0xffffffffu, ls0, 2);
    ls1 += __shfl_xor_sync(0xffffffffu, ls1, 1);
    ls1 += __shfl_xor_sync(0xffffffffu, ls1, 2);
    const float i0 = 1.f / fmaxf(ls0, 1e-30f);
    const float i1 = 1.f / fmaxf(ls1, 1e-30f);

    const int r0 = q0 + (wid << 4) + (lane >> 2);
    const int col = h * 64 + ((lane & 3) << 1);
#pragma unroll
    for (int dt = 0; dt < 8; dt++) {
        uint32_t h0, l0, h1, l1;
        pack_pair_f16(oacc[dt][0] * i0, oacc[dt][1] * i0, h0, l0);
        pack_pair_f16(oacc[dt][2] * i1, oacc[dt][3] * i1, h1, l1);
        size_t g0 = (rowbase + r0) * INNER + col + dt * 8;
        size_t g1 = (rowbase + r0 + 8) * INNER + col + dt * 8;
        *(uint32_t*)(oh + g0) = h0;
        *(uint32_t*)(ol + g0) = l0;
        *(uint32_t*)(oh + g1) = h1;
        *(uint32_t*)(ol + g1) = l1;
    }
}

// ---------------------------------------------------------------------------
// In-place LayerNorm (biased variance), one 256-thread block per row.
// ---------------------------------------------------------------------------
__global__ __launch_bounds__(256) void ln_kernel(
    float* __restrict__ Y, const float* __restrict__ gamma,
    const float* __restrict__ beta)
{
    const int row = blockIdx.x;
    float* y = Y + (size_t)row * DD;
    const int tid = threadIdx.x;

    float v[4];
    float s = 0.f, ss = 0.f;
#pragma unroll
    for (int i = 0; i < 4; i++) {
        v[i] = y[tid + (i << 8)];
        s += v[i];
        ss += v[i] * v[i];
    }
#pragma unroll
    for (int o = 16; o; o >>= 1) {
        s  += __shfl_xor_sync(0xffffffffu, s, o);
        ss += __shfl_xor_sync(0xffffffffu, ss, o);
    }
    __shared__ float rs[8], rss[8], mv[2];
    int w = tid >> 5, lane = tid & 31;
    if (!lane) { rs[w] = s; rss[w] = ss; }
    __syncthreads();
    if (tid == 0) {
        float S = 0.f, SS = 0.f;
#pragma unroll
        for (int i = 0; i < 8; i++) { S += rs[i]; SS += rss[i]; }
        float mean = S * (1.f / 1024.f);
        float var  = SS * (1.f / 1024.f) - mean * mean;
        mv[0] = mean;
        mv[1] = rsqrtf(var + 1e-5f);
    }
    __syncthreads();
    float mean = mv[0], rstd = mv[1];
#pragma unroll
    for (int i = 0; i < 4; i++) {
        int d = tid + (i << 8);
        y[d] = (v[i] - mean) * rstd * gamma[d] + beta[d];
    }
}

// ---------------------------------------------------------------------------
// Launch
// ---------------------------------------------------------------------------
extern "C" void kernel_launch(void* const* d_in, const int* in_sizes, int n_in,
                              void* d_out, int out_size)
{
    const float* x     = (const float*)d_in[0];
    const float* w_qkv = (const float*)d_in[2];
    const float* w_out = (const float*)d_in[3];
    const float* b_out = (const float*)d_in[4];
    const float* gamma = (const float*)d_in[5];
    const float* beta  = (const float*)d_in[6];
    float* out = (float*)d_out;

    uint16_t *xh, *wqh, *woh, *qh, *vth, *ah, *al;
    cudaGetSymbolAddress((void**)&xh,  g_xh);
    cudaGetSymbolAddress((void**)&wqh, g_wqh);
    cudaGetSymbolAddress((void**)&woh, g_woh);
    cudaGetSymbolAddress((void**)&qh,  g_qh);
    cudaGetSymbolAddress((void**)&vth, g_vth);
    cudaGetSymbolAddress((void**)&ah,  g_ah);
    cudaGetSymbolAddress((void**)&al,  g_al);

    const int SMEM_T1 = 4 * MTILE_B;   // 73728
    const int SMEM_T2 = 6 * MTILE_B;   // 110592
    cudaFuncSetAttribute(f16_gemm<1, true>,
                         cudaFuncAttributeMaxDynamicSharedMemorySize, SMEM_T1);
    cudaFuncSetAttribute(f16_gemm<2, false>,
                         cudaFuncAttributeMaxDynamicSharedMemorySize, SMEM_T2);
    cudaFuncSetAttribute(attn_kernel,
                         cudaFuncAttributeMaxDynamicSharedMemorySize,
                         AT_SMEM_BYTES);

    // 0) Round x and weights to fp16 (1-term)
    round_f16_kernel<<<(M1 * DD / 4 + 255) / 256, 256>>>(x, xh, M1 * DD / 4);
    round_f16_kernel<<<(QKV_N * DD / 4 + 255) / 256, 256>>>(w_qkv, wqh,
                                                            QKV_N * DD / 4);
    round_f16_kernel<<<(DD * INNER / 4 + 255) / 256, 256>>>(w_out, woh,
                                                            DD * INNER / 4);

    // 1) QKV projection (1-term A): Q,K -> fp16 qkv; V -> transposed fp16 VT
    f16_gemm<1, true><<<dim3(QKV_N / 128, M1 / 128), 256, SMEM_T1>>>(
        xh, nullptr, wqh, nullptr, nullptr, qh, vth, M1, QKV_N, DD);

    // 2) Attention (1-term fp16 MMA, KV double-buffered) -> fp16 2-term out
    attn_kernel<<<dim3(BB * HH, LL / 128), 256, AT_SMEM_BYTES>>>(
        qh, vth, ah, al);

    // 3) Output projection (2-term A) + bias -> d_out
    f16_gemm<2, false><<<dim3(INNER / 128, M1 / 128), 256, SMEM_T2>>>(
        ah, al, woh, b_out, out, nullptr, nullptr, M1, DD, INNER);

    // 4) LayerNorm in-place
    ln_kernel<<<M1, 256>>>(out, gamma, beta);
}

// round 17
// speedup vs baseline: 1.9175x; 1.0169x over previous
#include <cuda_runtime.h>
#include <cstdint>
#include <cstddef>

// Problem constants
#define BB 4
#define LL 1024
#define DD 1024
#define HH 16
#define INNER 1024          // H*HD
#define M1 4096             // B*L
#define QKV_N 3072          // 3*INNER

// Scratch (static device allocations — allowed)
__device__ uint16_t g_xh[(size_t)M1 * DD];      // x fp16 (1-term)
__device__ uint16_t g_wqh[(size_t)QKV_N * DD];  // w_qkv fp16 (1-term)
__device__ uint16_t g_woh[(size_t)DD * INNER];  // w_out fp16 (1-term)
__device__ uint16_t g_qh[(size_t)M1 * QKV_N];   // qkv fp16 (Q,K used)
__device__ uint16_t g_vth[(size_t)HH * 64 * BB * LL];  // V^T fp16 [e][b][l]
__device__ uint16_t g_ah[(size_t)M1 * INNER];   // attention out (fp16 hi)
__device__ uint16_t g_al[(size_t)M1 * INNER];   // attention out (fp16 lo)

// ===========================================================================
// Portable PTX helpers
// ===========================================================================
__device__ __forceinline__ uint32_t smem_u32(const void* p) {
    uint32_t a;
    asm("{ .reg .u64 t; cvta.to.shared.u64 t, %1; cvt.u32.u64 %0, t; }"
        : "=r"(a) : "l"(p));
    return a;
}
__device__ __forceinline__ void cp_async16(uint32_t dst, const void* src) {
    asm volatile("cp.async.cg.shared.global [%0], [%1], 16;"
                 :: "r"(dst), "l"(src) : "memory");
}
#define CP_COMMIT() asm volatile("cp.async.commit_group;" ::: "memory")
#define CP_WAIT(n)  asm volatile("cp.async.wait_group %0;" :: "n"(n) : "memory")

__device__ __forceinline__ void ldsm_x4(uint32_t* r, uint32_t addr) {
    asm volatile("ldmatrix.sync.aligned.m8n8.x4.shared.b16 {%0,%1,%2,%3}, [%4];"
                 : "=r"(r[0]), "=r"(r[1]), "=r"(r[2]), "=r"(r[3]) : "r"(addr));
}
__device__ __forceinline__ void mma_f16(float* d, const uint32_t* a,
                                        const uint32_t* b) {
    asm volatile(
        "mma.sync.aligned.m16n8k16.row.col.f32.f16.f16.f32 "
        "{%0,%1,%2,%3}, {%4,%5,%6,%7}, {%8,%9}, {%0,%1,%2,%3};"
        : "+f"(d[0]), "+f"(d[1]), "+f"(d[2]), "+f"(d[3])
        : "r"(a[0]), "r"(a[1]), "r"(a[2]), "r"(a[3]), "r"(b[0]), "r"(b[1]));
}
// ---- fp16 pack ----
__device__ __forceinline__ uint32_t cvt2f16(float e, float o) {
    uint32_t r;
    asm("cvt.rn.f16x2.f32 %0, %1, %2;" : "=r"(r) : "f"(o), "f"(e));
    return r;
}
__device__ __forceinline__ float f16lo2f(uint32_t h) {
    float f;
    asm("{ .reg .f16 a, b; mov.b32 {a, b}, %1; cvt.f32.f16 %0, a; }"
        : "=f"(f) : "r"(h));
    return f;
}
__device__ __forceinline__ float f16hi2f(uint32_t h) {
    float f;
    asm("{ .reg .f16 a, b; mov.b32 {a, b}, %1; cvt.f32.f16 %0, b; }"
        : "=f"(f) : "r"(h));
    return f;
}
__device__ __forceinline__ void pack_pair_f16(float e, float o,
                                              uint32_t& hi, uint32_t& lo) {
    uint32_t h = cvt2f16(e, o);
    float re = e - f16lo2f(h);
    float ro = o - f16hi2f(h);
    hi = h;
    lo = cvt2f16(re, ro);
}
__device__ __forceinline__ float fast_ex2(float x) {
    float r;
    asm("ex2.approx.ftz.f32 %0, %1;" : "=f"(r) : "f"(x));
    return r;
}

// ===========================================================================
// Fused round kernel: x, w_qkv, w_out -> fp16 in one launch (segmented).
// ===========================================================================
#define X4  (M1 * DD / 4)            // 1048576 uint-4 groups
#define WQ4 (QKV_N * DD / 4)         // 786432
#define WO4 (DD * INNER / 4)         // 262144

__global__ __launch_bounds__(256) void round3_kernel(
    const float* __restrict__ x, const float* __restrict__ wq,
    const float* __restrict__ wo,
    uint16_t* __restrict__ xh, uint16_t* __restrict__ wqh,
    uint16_t* __restrict__ woh)
{
    int idx = blockIdx.x * blockDim.x + threadIdx.x;
    const float* src;
    uint16_t* dst;
    int off;
    if (idx < X4) {
        src = x; dst = xh; off = idx;
    } else if (idx < X4 + WQ4) {
        src = wq; dst = wqh; off = idx - X4;
    } else if (idx < X4 + WQ4 + WO4) {
        src = wo; dst = woh; off = idx - X4 - WQ4;
    } else {
        return;
    }
    float4 v = ((const float4*)src)[off];
    ((uint2*)dst)[off] = make_uint2(cvt2f16(v.x, v.y), cvt2f16(v.z, v.w));
}

// ===========================================================================
// FP16 GEMM (NT), TERMS-term A: C = (Ah[+Al]) Bh^T. 128x128 tile,
// K-chunks of 64, 8 warps 2Mx4N, 2-stage cp.async pipeline.
// TERMS==1 mainloop: A-ldsm hoisted per ks, B-frags double-buffered.
// SPLIT_OUT: Q,K cols -> 1-term fp16 qkv; V cols (n0>=2048) -> transposed
// fp16 VT [e][b*1024+l] via smem transpose.
// ===========================================================================
#define BSTR 72                         // smem row stride (elems) = 144 B
#define MTILE_B (128 * BSTR * 2)        // 18432 bytes per matrix tile
#define TSTR 136                         // transpose tile stride (elems)

template <int TERMS, bool SPLIT_OUT>
__global__ __launch_bounds__(256) void f16_gemm(
    const uint16_t* __restrict__ Ah, const uint16_t* __restrict__ Al,
    const uint16_t* __restrict__ Bh,
    const float* __restrict__ bias, float* __restrict__ C,
    uint16_t* __restrict__ outH,
    uint16_t* __restrict__ vtH,
    int M, int N, int K)
{
    extern __shared__ char smraw[];
    const uint32_t sb = smem_u32(smraw);
    const int tid  = threadIdx.x;
    const int wid  = tid >> 5, lane = tid & 31;
    const int m0   = blockIdx.y << 7, n0 = blockIdx.x << 7;
    const int wm   = (wid & 1) << 6;
    const int wn   = (wid >> 1) << 5;

    const uint32_t STG = (uint32_t)(TERMS + 1) * MTILE_B;
    uint32_t stg[2] = { sb, sb + STG };

    // loads: 128 rows x 8 16B-units per matrix -> 4 units per thread
    int lrw[4]; uint32_t so[4];
#pragma unroll
    for (int i = 0; i < 4; i++) {
        int idx = tid + (i << 8);
        int row = idx >> 3, c8 = idx & 7;
        lrw[i] = row;
        so[i] = (uint32_t)(row * BSTR + c8 * 8) * 2;
    }
    const int lco = (tid & 7) * 8;
    const uint16_t* gAh = Ah + (size_t)m0 * K + lco;
    const uint16_t* gAl = (TERMS == 2) ? (Al + (size_t)m0 * K + lco) : nullptr;
    const uint16_t* gBh = Bh + (size_t)n0 * K + lco;

    float acc[4][4][4];
#pragma unroll
    for (int i = 0; i < 4; i++)
#pragma unroll
        for (int j = 0; j < 4; j++)
#pragma unroll
            for (int k = 0; k < 4; k++) acc[i][j][k] = 0.f;

    const uint32_t arow = (uint32_t)(wm + (lane & 15));
    const uint32_t acol = (uint32_t)((lane >> 4) << 3);
    const uint32_t brow = (uint32_t)(wn + (lane & 7) + ((lane >> 4) & 1) * 8);
    const uint32_t bcol = (uint32_t)(((lane >> 3) & 1) << 3);

    const int NCH = K >> 6;             // 64-wide chunks

    // prologue: chunk 0 -> stage 0
    {
        uint32_t d = stg[0];
#pragma unroll
        for (int i = 0; i < 4; i++) {
            size_t g = (size_t)lrw[i] * K;
            cp_async16(d + 0 * MTILE_B + so[i], gAh + g);
            if (TERMS == 2)
                cp_async16(d + 1 * MTILE_B + so[i], gAl + g);
            cp_async16(d + TERMS * MTILE_B + so[i], gBh + g);
        }
    }
    CP_COMMIT();

    for (int ch = 0; ch < NCH; ch++) {
        const int s = ch & 1;
        CP_WAIT(0);
        __syncthreads();   // chunk ch visible; prior reads of stg[1-s] done
        if (ch + 1 < NCH) {
            const int k0 = (ch + 1) << 6;
            uint32_t d = stg[1 - s];
#pragma unroll
            for (int i = 0; i < 4; i++) {
                size_t g = (size_t)lrw[i] * K + k0;
                cp_async16(d + 0 * MTILE_B + so[i], gAh + g);
                if (TERMS == 2)
                    cp_async16(d + 1 * MTILE_B + so[i], gAl + g);
                cp_async16(d + TERMS * MTILE_B + so[i], gBh + g);
            }
            CP_COMMIT();
        }

        const uint32_t AHB = stg[s];
        const uint32_t ALB = stg[s] + MTILE_B;           // valid if TERMS==2
        const uint32_t BHB = stg[s] + TERMS * MTILE_B;

        if (TERMS == 1) {
            // B-frag double buffer across ks; A-ldsm hoisted per ks.
            uint32_t bf[2][8];
            ldsm_x4(&bf[0][0], BHB + (brow * BSTR + bcol) * 2);
            ldsm_x4(&bf[0][4], BHB + ((brow + 16) * BSTR + bcol) * 2);
#pragma unroll
            for (int ks = 0; ks < 4; ks++) {
                const int cur = ks & 1;
                const uint32_t kadd = (uint32_t)(ks * 32);
                uint32_t af[4][4];
#pragma unroll
                for (int mi = 0; mi < 4; mi++)
                    ldsm_x4(af[mi],
                            AHB + ((arow + mi * 16) * BSTR + acol) * 2 + kadd);
                if (ks < 3) {
                    const uint32_t kn = kadd + 32;
                    ldsm_x4(&bf[1 - cur][0], BHB + (brow * BSTR + bcol) * 2 + kn);
                    ldsm_x4(&bf[1 - cur][4],
                            BHB + ((brow + 16) * BSTR + bcol) * 2 + kn);
                }
#pragma unroll
                for (int mi = 0; mi < 4; mi++)
#pragma unroll
                    for (int nj = 0; nj < 4; nj++)
                        mma_f16(acc[mi][nj], af[mi],
                                &bf[cur][(nj >> 1) * 4 + (nj & 1) * 2]);
            }
        } else {
#pragma unroll
            for (int ks = 0; ks < 4; ks++) {
                const uint32_t kadd = (uint32_t)(ks * 32);
                uint32_t bh_[2][4];
#pragma unroll
                for (int j = 0; j < 2; j++)
                    ldsm_x4(bh_[j],
                            BHB + ((brow + j * 16) * BSTR + bcol) * 2 + kadd);
#pragma unroll
                for (int mip = 0; mip < 2; mip++) {
                    const uint32_t off0 =
                        ((arow + (2 * mip) * 16) * BSTR + acol) * 2 + kadd;
                    const uint32_t off1 =
                        ((arow + (2 * mip + 1) * 16) * BSTR + acol) * 2 + kadd;
                    uint32_t ah0[4], ah1[4], al0[4], al1[4];
                    ldsm_x4(ah0, AHB + off0);
                    ldsm_x4(ah1, AHB + off1);
                    ldsm_x4(al0, ALB + off0);
                    ldsm_x4(al1, ALB + off1);
#pragma unroll
                    for (int nj = 0; nj < 4; nj++)
                        mma_f16(acc[2 * mip][nj],     ah0, bh_[nj >> 1] + (nj & 1) * 2);
#pragma unroll
                    for (int nj = 0; nj < 4; nj++)
                        mma_f16(acc[2 * mip + 1][nj], ah1, bh_[nj >> 1] + (nj & 1) * 2);
#pragma unroll
                    for (int nj = 0; nj < 4; nj++)
                        mma_f16(acc[2 * mip][nj],     al0, bh_[nj >> 1] + (nj & 1) * 2);
#pragma unroll
                    for (int nj = 0; nj < 4; nj++)
                        mma_f16(acc[2 * mip + 1][nj], al1, bh_[nj >> 1] + (nj & 1) * 2);
                }
            }
        }
    }

    const int rbase = m0 + wm + (lane >> 2);
    const int cbase = n0 + wn + ((lane & 3) << 1);

    if (SPLIT_OUT && n0 >= 2 * INNER) {
        // ---- V columns: transpose via smem (1 pass), store fp16 VT ----
        uint16_t* T = (uint16_t*)smraw;
        const int b  = m0 >> 10;
        const int l0 = m0 & 1023;
        __syncthreads();   // mainloop reads done
        const int rloc = wm + (lane >> 2);
        const int cloc = wn + ((lane & 3) << 1);
#pragma unroll
        for (int nj = 0; nj < 4; nj++) {
#pragma unroll
            for (int mi = 0; mi < 4; mi++) {
                uint32_t w0 = cvt2f16(acc[mi][nj][0], acc[mi][nj][1]);
                uint32_t w1 = cvt2f16(acc[mi][nj][2], acc[mi][nj][3]);
                int c = cloc + nj * 8;
                int r = rloc + mi * 16;
                T[c * TSTR + r]           = (uint16_t)(w0 & 0xffffu);
                T[(c + 1) * TSTR + r]     = (uint16_t)(w0 >> 16);
                T[c * TSTR + r + 8]       = (uint16_t)(w1 & 0xffffu);
                T[(c + 1) * TSTR + r + 8] = (uint16_t)(w1 >> 16);
            }
        }
        __syncthreads();
        // Drain FULL tile: 128 cols x 16 8-row units.
#pragma unroll
        for (int i = 0; i < 8; i++) {
            int idx = tid + (i << 8);
            int c = idx >> 4, u = idx & 15;
            int e = n0 - 2 * INNER + c;
            size_t dst = ((size_t)e * BB + b) * LL + l0 + u * 8;
            *(uint4*)(vtH + dst) = *(const uint4*)(T + c * TSTR + u * 8);
        }
    } else {
#pragma unroll
        for (int nj = 0; nj < 4; nj++) {
            const int col = cbase + nj * 8;
            if (SPLIT_OUT) {
#pragma unroll
                for (int mi = 0; mi < 4; mi++) {
                    const int r0 = rbase + mi * 16;
                    uint32_t h0 = cvt2f16(acc[mi][nj][0], acc[mi][nj][1]);
                    uint32_t h1 = cvt2f16(acc[mi][nj][2], acc[mi][nj][3]);
                    *(uint32_t*)(outH + (size_t)r0 * N + col) = h0;
                    *(uint32_t*)(outH + (size_t)(r0 + 8) * N + col) = h1;
                }
            } else {
                float b0 = bias[col], b1 = bias[col + 1];
#pragma unroll
                for (int mi = 0; mi < 4; mi++) {
                    const int r0 = rbase + mi * 16;
                    float2 v0 = { acc[mi][nj][0] + b0, acc[mi][nj][1] + b1 };
                    float2 v1 = { acc[mi][nj][2] + b0, acc[mi][nj][3] + b1 };
                    *(float2*)(C + (size_t)r0 * N + col) = v0;
                    *(float2*)(C + (size_t)(r0 + 8) * N + col) = v1;
                }
            }
        }
    }
}

// ===========================================================================
// Tensor-core attention, 1-term fp16 (arithmetic unchanged since round 13).
// KV cp.async double-buffered. NEW: register double-buffering of K-frags in
// the S loop and V-frags in the PV loop (same MMA order -> bit-identical).
// ===========================================================================
#define AT_STR 72
#define AQ 0
#define AKV (128 * AT_STR)              // stage 0 base (elems)
#define ASTG (128 * AT_STR)             // stage stride: K 64 rows + V 64 rows
#define AT_ELEMS (AKV + 2 * ASTG)
#define AT_SMEM_BYTES (AT_ELEMS * 2)    // 55296 bytes

__global__ __launch_bounds__(256) void attn_kernel(
    const uint16_t* __restrict__ qh,
    const uint16_t* __restrict__ vth,
    uint16_t* __restrict__ oh, uint16_t* __restrict__ ol)
{
    extern __shared__ uint16_t sm16[];
    const uint32_t sb = smem_u32(sm16);
    const int tid = threadIdx.x, wid = tid >> 5, lane = tid & 31;
    const int bh = blockIdx.x, b = bh >> 4, h = bh & 15;
    const int q0 = blockIdx.y << 7;
    const size_t rowbase = (size_t)b * LL;

    // ---- Q tile: 128 rows x 64 cols fp16 (plain loads, once) ----
#pragma unroll
    for (int i = 0; i < 4; i++) {
        int idx = tid + (i << 8);
        if (idx < 1024) {
            int r = idx >> 3, c8 = idx & 7;
            size_t g = (rowbase + q0 + r) * QKV_N + h * 64 + c8 * 8;
            *(uint4*)(sm16 + AQ + r * AT_STR + c8 * 8) = *(const uint4*)(qh + g);
        }
    }

    // ---- per-thread KV cp.async slots ----
    const int lr = tid >> 3, lc8 = tid & 7;
    const uint32_t KV0 = sb + (uint32_t)AKV * 2;
    const uint32_t STGB = (uint32_t)ASTG * 2;
    const uint32_t VOFF = (uint32_t)(64 * AT_STR) * 2;

    // prologue: KV tile 0 -> stage 0
    {
        uint32_t d = KV0;
#pragma unroll
        for (int i = 0; i < 2; i++) {
            int r = lr + i * 32;
            uint32_t dl = (uint32_t)(r * AT_STR + lc8 * 8) * 2;
            size_t gk = (rowbase + r) * QKV_N + INNER + h * 64 + lc8 * 8;
            size_t gv = ((size_t)(h * 64 + r) * BB + b) * LL + lc8 * 8;
            cp_async16(d + dl, qh + gk);
            cp_async16(d + VOFF + dl, vth + gv);
        }
    }
    CP_COMMIT();
    __syncthreads();   // Q tile visible for ldsm

    uint32_t qf[4][4];
    {
        const uint32_t qrow = (uint32_t)((wid << 4) + (lane & 15));
        const uint32_t cc = (uint32_t)((lane >> 4) << 3);
#pragma unroll
        for (int ks = 0; ks < 4; ks++) {
            uint32_t off = (uint32_t)(qrow * AT_STR + ks * 16 + cc) * 2;
            ldsm_x4(qf[ks], sb + AQ * 2 + off);
        }
    }

    float oacc[8][4];
#pragma unroll
    for (int i = 0; i < 8; i++)
#pragma unroll
        for (int j = 0; j < 4; j++) oacc[i][j] = 0.f;
    float ls0 = 0.f, ls1 = 0.f;

    const float CE = 0.125f * 1.4426950408889634f;
    // ldsm lane-address components (shared by S and PV loops)
    const uint32_t lrow8 = (uint32_t)((lane & 7) + ((lane >> 4) & 1) * 8);
    const uint32_t lcol8 = (uint32_t)(((lane >> 3) & 1) * 8);

    for (int kt = 0; kt < 16; kt++) {
        CP_WAIT(0);
        __syncthreads();   // KV(kt) visible; reads of other stage done

        if (kt + 1 < 16) {
            uint32_t d = KV0 + ((kt + 1) & 1) * STGB;
#pragma unroll
            for (int i = 0; i < 2; i++) {
                int r = lr + i * 32;
                uint32_t dl = (uint32_t)(r * AT_STR + lc8 * 8) * 2;
                size_t gk = (rowbase + (kt + 1) * 64 + r) * QKV_N + INNER
                            + h * 64 + lc8 * 8;
                size_t gv = ((size_t)(h * 64 + r) * BB + b) * LL
                            + (kt + 1) * 64 + lc8 * 8;
                cp_async16(d + dl, qh + gk);
                cp_async16(d + VOFF + dl, vth + gv);
            }
            CP_COMMIT();
        }

        const uint32_t base = KV0 + (kt & 1) * STGB;
        const uint32_t KB = base, VBa = base + VOFF;

        // ---- S = Q K^T (1-term fp16), K-frags double-buffered ----
        float p[8][4];
#pragma unroll
        for (int i = 0; i < 8; i++)
#pragma unroll
            for (int j = 0; j < 4; j++) p[i][j] = 0.f;

        {
            uint32_t kf[2][4];
            // it = ks*4 + njp; addr(it) = KB + ((njp*16+lrow8)*AT_STR + ks*16+lcol8)*2
            ldsm_x4(kf[0], KB + (lrow8 * AT_STR + lcol8) * 2);
#pragma unroll
            for (int it = 0; it < 16; it++) {
                const int cur = it & 1;
                const int ks = it >> 2, njp = it & 3;
                if (it < 15) {
                    const int ks1 = (it + 1) >> 2, njp1 = (it + 1) & 3;
                    uint32_t ad = KB + (uint32_t)((njp1 * 16 + lrow8) * AT_STR
                                                  + ks1 * 16 + lcol8) * 2;
                    ldsm_x4(kf[1 - cur], ad);
                }
                mma_f16(p[2 * njp],     qf[ks], kf[cur]);
                mma_f16(p[2 * njp + 1], qf[ks], kf[cur] + 2);
            }
        }

        // ---- exp (clamped, exponent shifted -8 for fp16 range) ----
#pragma unroll
        for (int nt = 0; nt < 8; nt++) {
#pragma unroll
            for (int q = 0; q < 4; q++) {
                float a_ = fminf(p[nt][q] * CE, 80.f) - 8.f;
                p[nt][q] = fast_ex2(a_);
            }
            ls0 += p[nt][0] + p[nt][1];
            ls1 += p[nt][2] + p[nt][3];
        }

        // ---- repack P -> fp16 A-frags ----
        uint32_t pa[4][4];
#pragma unroll
        for (int ks = 0; ks < 4; ks++) {
            pa[ks][0] = cvt2f16(p[2 * ks][0],     p[2 * ks][1]);
            pa[ks][1] = cvt2f16(p[2 * ks][2],     p[2 * ks][3]);
            pa[ks][2] = cvt2f16(p[2 * ks + 1][0], p[2 * ks + 1][1]);
            pa[ks][3] = cvt2f16(p[2 * ks + 1][2], p[2 * ks + 1][3]);
        }

        // ---- O += P V (1-term fp16), V-frags double-buffered ----
        {
            uint32_t vf[2][4];
            // it = ks*4 + dtp; addr = VBa + ((dtp*16+lrow8)*AT_STR + ks*16+lcol8)*2
            ldsm_x4(vf[0], VBa + (lrow8 * AT_STR + lcol8) * 2);
#pragma unroll
            for (int it = 0; it < 16; it++) {
                const int cur = it & 1;
                const int ks = it >> 2, dtp = it & 3;
                if (it < 15) {
                    const int ks1 = (it + 1) >> 2, dtp1 = (it + 1) & 3;
                    uint32_t ad = VBa + (uint32_t)((dtp1 * 16 + lrow8) * AT_STR
                                                   + ks1 * 16 + lcol8) * 2;
                    ldsm_x4(vf[1 - cur], ad);
                }
                mma_f16(oacc[2 * dtp],     pa[ks], vf[cur]);
                mma_f16(oacc[2 * dtp + 1], pa[ks], vf[cur] + 2);
            }
        }
    }

    // ---- epilogue: normalize + fp16 2-term split-store ----
    ls0 += __shfl_xor_sync(0xffffffffu, ls0, 1);
    ls0 += __shfl_xor_sync(0xffffffffu, ls0, 2);
    ls1 += __shfl_xor_sync(0xffffffffu, ls1, 1);
    ls1 += __shfl_xor_sync(0xffffffffu, ls1, 2);
    const float i0 = 1.f / fmaxf(ls0, 1e-30f);
    const float i1 = 1.f / fmaxf(ls1, 1e-30f);

    const int r0 = q0 + (wid << 4) + (lane >> 2);
    const int col = h * 64 + ((lane & 3) << 1);
#pragma unroll
    for (int dt = 0; dt < 8; dt++) {
        uint32_t h0, l0, h1, l1;
        pack_pair_f16(oacc[dt][0] * i0, oacc[dt][1] * i0, h0, l0);
        pack_pair_f16(oacc[dt][2] * i1, oacc[dt][3] * i1, h1, l1);
        size_t g0 = (rowbase + r0) * INNER + col + dt * 8;
        size_t g1 = (rowbase + r0 + 8) * INNER + col + dt * 8;
        *(uint32_t*)(oh + g0) = h0;
        *(uint32_t*)(ol + g0) = l0;
        *(uint32_t*)(oh + g1) = h1;
        *(uint32_t*)(ol + g1) = l1;
    }
}

// ---------------------------------------------------------------------------
// In-place LayerNorm (biased variance), one 256-thread block per row.
// ---------------------------------------------------------------------------
__global__ __launch_bounds__(256) void ln_kernel(
    float* __restrict__ Y, const float* __restrict__ gamma,
    const float* __restrict__ beta)
{
    const int row = blockIdx.x;
    float* y = Y + (size_t)row * DD;
    const int tid = threadIdx.x;

    float v[4];
    float s = 0.f, ss = 0.f;
#pragma unroll
    for (int i = 0; i < 4; i++) {
        v[i] = y[tid + (i << 8)];
        s += v[i];
        ss += v[i] * v[i];
    }
#pragma unroll
    for (int o = 16; o; o >>= 1) {
        s  += __shfl_xor_sync(0xffffffffu, s, o);
        ss += __shfl_xor_sync(0xffffffffu, ss, o);
    }
    __shared__ float rs[8], rss[8], mv[2];
    int w = tid >> 5, lane = tid & 31;
    if (!lane) { rs[w] = s; rss[w] = ss; }
    __syncthreads();
    if (tid == 0) {
        float S = 0.f, SS = 0.f;
#pragma unroll
        for (int i = 0; i < 8; i++) { S += rs[i]; SS += rss[i]; }
        float mean = S * (1.f / 1024.f);
        float var  = SS * (1.f / 1024.f) - mean * mean;
        mv[0] = mean;
        mv[1] = rsqrtf(var + 1e-5f);
    }
    __syncthreads();
    float mean = mv[0], rstd = mv[1];
#pragma unroll
    for (int i = 0; i < 4; i++) {
        int d = tid + (i << 8);
        y[d] = (v[i] - mean) * rstd * gamma[d] + beta[d];
    }
}

// ---------------------------------------------------------------------------
// Launch
// ---------------------------------------------------------------------------
extern "C" void kernel_launch(void* const* d_in, const int* in_sizes, int n_in,
                              void* d_out, int out_size)
{
    const float* x     = (const float*)d_in[0];
    const float* w_qkv = (const float*)d_in[2];
    const float* w_out = (const float*)d_in[3];
    const float* b_out = (const float*)d_in[4];
    const float* gamma = (const float*)d_in[5];
    const float* beta  = (const float*)d_in[6];
    float* out = (float*)d_out;

    uint16_t *xh, *wqh, *woh, *qh, *vth, *ah, *al;
    cudaGetSymbolAddress((void**)&xh,  g_xh);
    cudaGetSymbolAddress((void**)&wqh, g_wqh);
    cudaGetSymbolAddress((void**)&woh, g_woh);
    cudaGetSymbolAddress((void**)&qh,  g_qh);
    cudaGetSymbolAddress((void**)&vth, g_vth);
    cudaGetSymbolAddress((void**)&ah,  g_ah);
    cudaGetSymbolAddress((void**)&al,  g_al);

    const int SMEM_T1 = 4 * MTILE_B;   // 73728
    const int SMEM_T2 = 6 * MTILE_B;   // 110592
    cudaFuncSetAttribute(f16_gemm<1, true>,
                         cudaFuncAttributeMaxDynamicSharedMemorySize, SMEM_T1);
    cudaFuncSetAttribute(f16_gemm<2, false>,
                         cudaFuncAttributeMaxDynamicSharedMemorySize, SMEM_T2);
    cudaFuncSetAttribute(attn_kernel,
                         cudaFuncAttributeMaxDynamicSharedMemorySize,
                         AT_SMEM_BYTES);

    // 0) Round x + both weights to fp16 in ONE launch
    round3_kernel<<<(X4 + WQ4 + WO4 + 255) / 256, 256>>>(
        x, w_qkv, w_out, xh, wqh, woh);

    // 1) QKV projection (1-term A): Q,K -> fp16 qkv; V -> transposed fp16 VT
    f16_gemm<1, true><<<dim3(QKV_N / 128, M1 / 128), 256, SMEM_T1>>>(
        xh, nullptr, wqh, nullptr, nullptr, qh, vth, M1, QKV_N, DD);

    // 2) Attention (1-term fp16 MMA, KV + frag double-buffered)
    attn_kernel<<<dim3(BB * HH, LL / 128), 256, AT_SMEM_BYTES>>>(
        qh, vth, ah, al);

    // 3) Output projection (2-term A) + bias -> d_out
    f16_gemm<2, false><<<dim3(INNER / 128, M1 / 128), 256, SMEM_T2>>>(
        ah, al, woh, b_out, out, nullptr, nullptr, M1, DD, INNER);

    // 4) LayerNorm in-place
    ln_kernel<<<M1, 256>>>(out, gamma, beta);
}